// round 3
// baseline (speedup 1.0000x reference)
#include <cuda_runtime.h>
#include <math.h>

// ---------------- problem constants ----------------
#define BATCH 64
#define TDEC  150
#define NVOC  48
#define LHID  256
#define SHID  512
#define NMLP  128

typedef unsigned long long ull;

// ---------------- device scratch ----------------
__device__ float g_xw0[64*1024*1024];
__device__ float g_xw1[64*1024*1024];
__device__ float g_out0[64*1024*512];
__device__ float g_out1[64*512*512];
__device__ float g_feats[64*256*512];
__device__ float g_cf[64*256*128];
__device__ float g_h[2*2*64*256];          // [parity][dir][b][256]
__device__ float g_c[2*64*256];
__device__ float g_dh[2*64*512];
__device__ float g_ctx[64*512];
__device__ float g_phiWt[512*128];
__device__ unsigned g_barE[2];             // per-direction encoder barriers
__device__ unsigned g_barD;                // decoder barrier

// ---------------- software grid barrier (counter reset pre-launch) ----------
__device__ __forceinline__ void gbar(unsigned* ctr, unsigned& epoch, unsigned nb)
{
    __syncthreads();
    if (threadIdx.x == 0) {
        __threadfence();
        atomicAdd(ctr, 1u);
        unsigned target = epoch + nb;
        volatile unsigned* p = ctr;
        while (*p < target) { }
    }
    epoch += nb;
    __syncthreads();
}

// ---------------- packed fp32x2 FMA (SASS FFMA2) ----------------
__device__ __forceinline__ void fma2(ull& d, ull a, ull b)
{
    asm("fma.rn.f32x2 %0, %1, %2, %0;" : "+l"(d) : "l"(a), "l"(b));
}

union UP { float4 f; ull u[2]; };
union U2 { ull u; float2 f; };

// ---------------- fp32 GEMM via f32x2: C[M,N] = A@W^T + bias, opt relu -------
// Tile 128x128, BK=16, 256 threads (16x16), 8x8 per thread.
// Requires M%128==0, N%128==0, K%16==0 (true at all call sites).
__global__ __launch_bounds__(256) void gemm_bias(
    const float* __restrict__ A, const float* __restrict__ W,
    const float* __restrict__ bias, float* __restrict__ C,
    int M, int N, int K, int relu)
{
    __shared__ float As2[16 * 264];   // duplicated: As2[k][2m]=As2[k][2m+1]=A[m][k]
    __shared__ float Ws[16 * 136];    // Ws[k][n]
    int bm = blockIdx.y << 7, bn = blockIdx.x << 7;
    int tid = threadIdx.x;
    int ty = tid >> 4, tx = tid & 15;
    const float* Ap = A + (size_t)bm * K;
    const float* Wp = W + (size_t)bn * K;

    ull acc[8][4];
#pragma unroll
    for (int i = 0; i < 8; i++)
#pragma unroll
        for (int j = 0; j < 4; j++) acc[i][j] = 0ull;

    for (int k0 = 0; k0 < K; k0 += 16) {
#pragma unroll
        for (int j = 0; j < 2; j++) {
            int idx = tid + 256 * j;
            int r = idx >> 2, c = (idx & 3) << 2;
            float4 v = *(const float4*)&Ap[(size_t)r * K + k0 + c];
            *(float2*)&As2[(c + 0) * 264 + 2 * r] = make_float2(v.x, v.x);
            *(float2*)&As2[(c + 1) * 264 + 2 * r] = make_float2(v.y, v.y);
            *(float2*)&As2[(c + 2) * 264 + 2 * r] = make_float2(v.z, v.z);
            *(float2*)&As2[(c + 3) * 264 + 2 * r] = make_float2(v.w, v.w);
        }
#pragma unroll
        for (int j = 0; j < 2; j++) {
            int idx = tid + 256 * j;
            int r = idx >> 2, c = (idx & 3) << 2;
            float4 v = *(const float4*)&Wp[(size_t)r * K + k0 + c];
            Ws[(c + 0) * 136 + r] = v.x;
            Ws[(c + 1) * 136 + r] = v.y;
            Ws[(c + 2) * 136 + r] = v.z;
            Ws[(c + 3) * 136 + r] = v.w;
        }
        __syncthreads();
#pragma unroll
        for (int kk = 0; kk < 16; kk++) {
            UP a0, a1, a2, a3, w0, w1;
            a0.f = *(const float4*)&As2[kk * 264 + ty * 16 + 0];
            a1.f = *(const float4*)&As2[kk * 264 + ty * 16 + 4];
            a2.f = *(const float4*)&As2[kk * 264 + ty * 16 + 8];
            a3.f = *(const float4*)&As2[kk * 264 + ty * 16 + 12];
            w0.f = *(const float4*)&Ws[kk * 136 + tx * 8 + 0];
            w1.f = *(const float4*)&Ws[kk * 136 + tx * 8 + 4];
            ull aP[8] = {a0.u[0], a0.u[1], a1.u[0], a1.u[1],
                         a2.u[0], a2.u[1], a3.u[0], a3.u[1]};
#pragma unroll
            for (int i = 0; i < 8; i++) {
                fma2(acc[i][0], aP[i], w0.u[0]);
                fma2(acc[i][1], aP[i], w0.u[1]);
                fma2(acc[i][2], aP[i], w1.u[0]);
                fma2(acc[i][3], aP[i], w1.u[1]);
            }
        }
        __syncthreads();
    }
    float4 b0 = *(const float4*)&bias[bn + tx * 8];
    float4 b1 = *(const float4*)&bias[bn + tx * 8 + 4];
#pragma unroll
    for (int i = 0; i < 8; i++) {
        int m = bm + ty * 8 + i;
        U2 p0, p1, p2, p3;
        p0.u = acc[i][0]; p1.u = acc[i][1]; p2.u = acc[i][2]; p3.u = acc[i][3];
        float4 o0, o1;
        o0.x = p0.f.x + b0.x; o0.y = p0.f.y + b0.y;
        o0.z = p1.f.x + b0.z; o0.w = p1.f.y + b0.w;
        o1.x = p2.f.x + b1.x; o1.y = p2.f.y + b1.y;
        o1.z = p3.f.x + b1.z; o1.w = p3.f.y + b1.w;
        if (relu) {
            o0.x = fmaxf(o0.x, 0.f); o0.y = fmaxf(o0.y, 0.f);
            o0.z = fmaxf(o0.z, 0.f); o0.w = fmaxf(o0.w, 0.f);
            o1.x = fmaxf(o1.x, 0.f); o1.y = fmaxf(o1.y, 0.f);
            o1.z = fmaxf(o1.z, 0.f); o1.w = fmaxf(o1.w, 0.f);
        }
        *(float4*)&C[(size_t)m * N + bn + tx * 8] = o0;
        *(float4*)&C[(size_t)m * N + bn + tx * 8 + 4] = o1;
    }
}

// ---------------- persistent encoder scan (per-direction barrier) -----------
#define ENC_SMEM ((16 * 264 + 64 * 260) * 4)
__global__ __launch_bounds__(256) void enc_scan(
    const float* __restrict__ xw_f, const float* __restrict__ xw_b,
    const float* __restrict__ whh_f, const float* __restrict__ whh_b,
    float* __restrict__ out, int Tl)
{
    extern __shared__ float smem[];
    float* sh_w = smem;               // 16 x 256 (pitch 264)
    float* sh_x = smem + 16 * 264;    // 64 x 256 (pitch 260)

    int tid = threadIdx.x;
    int lane = tid & 31, wrp = tid >> 5;
    int u = wrp & 3, bh = wrp >> 2;
    int b = bh * 32 + lane;
    int dir = blockIdx.y;
    int hu0 = blockIdx.x << 2;
    int hu = hu0 + u;
    unsigned epoch = 0;
    const unsigned nb = gridDim.x;       // 64 blocks per direction
    unsigned* ctr = &g_barE[dir];

    const float* xw  = dir ? xw_b  : xw_f;
    const float* Whh = dir ? whh_b : whh_f;

    for (int i = tid; i < 16 * 64; i += 256) {
        int r = i >> 6, kq = (i & 63) << 2;
        int grow = ((r >> 2) << 8) + hu0 + (r & 3);
        *(float4*)&sh_w[r * 264 + kq] = *(const float4*)&Whh[(size_t)grow * 256 + kq];
    }

    float creg = 0.f;
    __stcg(&g_h[(size_t)(0 * 2 + dir) * 64 * 256 + b * 256 + hu], 0.f);
    gbar(ctr, epoch, nb);

    for (int t = 0; t < Tl; t++) {
        int tt = dir ? (Tl - 1 - t) : t;
        int pin = t & 1, pout = pin ^ 1;
        const float* hin = g_h + (size_t)(pin * 2 + dir) * 64 * 256;

        // prefetch gate pre-activations (strided DRAM gather) early
        size_t xi = ((size_t)b * Tl + tt) * 1024 + hu;
        float x0 = __ldg(&xw[xi]);
        float x1 = __ldg(&xw[xi + 256]);
        float x2 = __ldg(&xw[xi + 512]);
        float x3 = __ldg(&xw[xi + 768]);

        __syncthreads();
        for (int i = tid; i < 64 * 64; i += 256) {
            int bb = i >> 6, kq = (i & 63) << 2;
            *(float4*)&sh_x[bb * 260 + kq] = __ldcg((const float4*)&hin[bb * 256 + kq]);
        }
        __syncthreads();

        float acc0 = 0.f, acc1 = 0.f, acc2 = 0.f, acc3 = 0.f;
#pragma unroll 8
        for (int kk = 0; kk < 256; kk += 4) {
            float4 hv = *(const float4*)&sh_x[b * 260 + kk];
            float4 w0 = *(const float4*)&sh_w[(0 * 4 + u) * 264 + kk];
            float4 w1 = *(const float4*)&sh_w[(1 * 4 + u) * 264 + kk];
            float4 w2 = *(const float4*)&sh_w[(2 * 4 + u) * 264 + kk];
            float4 w3 = *(const float4*)&sh_w[(3 * 4 + u) * 264 + kk];
            acc0 += hv.x * w0.x + hv.y * w0.y + hv.z * w0.z + hv.w * w0.w;
            acc1 += hv.x * w1.x + hv.y * w1.y + hv.z * w1.z + hv.w * w1.w;
            acc2 += hv.x * w2.x + hv.y * w2.y + hv.z * w2.z + hv.w * w2.w;
            acc3 += hv.x * w3.x + hv.y * w3.y + hv.z * w3.z + hv.w * w3.w;
        }
        float zi = acc0 + x0;
        float zf = acc1 + x1;
        float zg = acc2 + x2;
        float zo = acc3 + x3;
        float si = 1.f / (1.f + expf(-zi));
        float sf = 1.f / (1.f + expf(-zf));
        float so = 1.f / (1.f + expf(-zo));
        float cn = sf * creg + si * tanhf(zg);
        float hn = so * tanhf(cn);
        creg = cn;
        __stcg(&g_h[(size_t)(pout * 2 + dir) * 64 * 256 + b * 256 + hu], hn);
        out[((size_t)b * Tl + tt) * 512 + dir * 256 + hu] = hn;
        gbar(ctr, epoch, nb);
    }
    g_c[(size_t)(dir * 64 + b) * 256 + hu] = creg;
}

// ---------------- persistent decoder (LSTM step + attention fused) ----------
#define DEC_SMEM ((16 * 1032 + 64 * 132 + 512 + 128 + 256 + 512 + 64 + 256) * 4)
__global__ __launch_bounds__(256) void dec_scan(
    const float* __restrict__ sWih, const float* __restrict__ sWhh,
    const float* __restrict__ sb, const int* __restrict__ gt,
    const float* __restrict__ phi_b,
    const float* __restrict__ fcW, const float* __restrict__ fcb,
    float* __restrict__ out_lps)
{
    extern __shared__ float smem[];
    float* sh_w  = smem;
    float* sh_x  = sh_w + 16 * 1032;
    float* sh_h  = sh_x + 64 * 132;
    float* sh_q  = sh_h + 512;
    float* sh_e  = sh_q + 128;
    float* sh_c2 = sh_e + 256;
    float* sh_l  = sh_c2 + 512;
    float* sr    = sh_l + 64;

    int tid = threadIdx.x;
    int lane = tid & 31, wrp = tid >> 5;
    int u = wrp & 3, bh = wrp >> 2;
    int b = bh * 32 + lane;
    int hu0 = blockIdx.x << 2;
    int hu = hu0 + u;
    unsigned epoch = 0;
    const unsigned nb = gridDim.x;
    unsigned* ctr = &g_barD;

    for (int i = tid; i < 16 * 256; i += 256) {
        int r = i >> 8, kq = (i & 255) << 2;
        int grow = (r >> 2) * SHID + hu0 + (r & 3);
        float4 v;
        if (kq < 512) v = *(const float4*)&sWih[(size_t)grow * 560 + 48 + kq];
        else          v = *(const float4*)&sWhh[(size_t)grow * 512 + (kq - 512)];
        *(float4*)&sh_w[r * 1032 + kq] = v;
    }

    float creg = 0.f;
    __stcg(&g_dh[(size_t)b * 512 + hu], 0.f);
    __stcg(&g_ctx[(size_t)b * 512 + hu], __ldg(&g_feats[(size_t)b * 256 * 512 + hu]));
    gbar(ctr, epoch, nb);

    float bi0 = sb[0 * SHID + hu], bi1 = sb[1 * SHID + hu];
    float bi2 = sb[2 * SHID + hu], bi3 = sb[3 * SHID + hu];

    for (int t = 0; t < TDEC; t++) {
        int pin = t & 1, pout = pin ^ 1;
        int tok = (t == 0) ? 0 : gt[b * TDEC + (t - 1)];
        float acc0 = sWih[(size_t)(0 * SHID + hu) * 560 + tok] + bi0;
        float acc1 = sWih[(size_t)(1 * SHID + hu) * 560 + tok] + bi1;
        float acc2 = sWih[(size_t)(2 * SHID + hu) * 560 + tok] + bi2;
        float acc3 = sWih[(size_t)(3 * SHID + hu) * 560 + tok] + bi3;

        const float* hin = g_dh + (size_t)pin * 64 * 512;
        for (int c = 0; c < 8; c++) {
            __syncthreads();
            const float* src = (c < 4) ? (g_ctx + (c << 7)) : (hin + ((c - 4) << 7));
            for (int i = tid; i < 64 * 32; i += 256) {
                int bb = i >> 5, kq = (i & 31) << 2;
                *(float4*)&sh_x[bb * 132 + kq] = __ldcg((const float4*)&src[(size_t)bb * 512 + kq]);
            }
            __syncthreads();
            const float* wp = sh_w + c * 128;
#pragma unroll 8
            for (int kk = 0; kk < 128; kk += 4) {
                float4 hv = *(const float4*)&sh_x[b * 132 + kk];
                float4 w0 = *(const float4*)&wp[(0 * 4 + u) * 1032 + kk];
                float4 w1 = *(const float4*)&wp[(1 * 4 + u) * 1032 + kk];
                float4 w2 = *(const float4*)&wp[(2 * 4 + u) * 1032 + kk];
                float4 w3 = *(const float4*)&wp[(3 * 4 + u) * 1032 + kk];
                acc0 += hv.x * w0.x + hv.y * w0.y + hv.z * w0.z + hv.w * w0.w;
                acc1 += hv.x * w1.x + hv.y * w1.y + hv.z * w1.z + hv.w * w1.w;
                acc2 += hv.x * w2.x + hv.y * w2.y + hv.z * w2.z + hv.w * w2.w;
                acc3 += hv.x * w3.x + hv.y * w3.y + hv.z * w3.z + hv.w * w3.w;
            }
        }
        float si = 1.f / (1.f + expf(-acc0));
        float sf = 1.f / (1.f + expf(-acc1));
        float so = 1.f / (1.f + expf(-acc3));
        float cn = sf * creg + si * tanhf(acc2);
        float hn = so * tanhf(cn);
        creg = cn;
        __stcg(&g_dh[(size_t)pout * 64 * 512 + b * 512 + hu], hn);
        gbar(ctr, epoch, nb);

        if (blockIdx.x < 64) {
            int bb = blockIdx.x;
            const float* h = g_dh + (size_t)pout * 64 * 512 + (size_t)bb * 512;
            for (int i = tid; i < 512; i += 256) sh_h[i] = __ldcg(&h[i]);
            __syncthreads();

            if (tid < 128) {
                float a0 = 0.f, a1 = 0.f, a2 = 0.f, a3 = 0.f;
                for (int k = 0; k < 512; k += 4) {
                    a0 += sh_h[k + 0] * g_phiWt[(k + 0) * 128 + tid];
                    a1 += sh_h[k + 1] * g_phiWt[(k + 1) * 128 + tid];
                    a2 += sh_h[k + 2] * g_phiWt[(k + 2) * 128 + tid];
                    a3 += sh_h[k + 3] * g_phiWt[(k + 3) * 128 + tid];
                }
                float q = a0 + a1 + a2 + a3 + phi_b[tid];
                sh_q[tid] = q > 0.f ? q : 0.f;
            }
            __syncthreads();

            {
                const float* cfp = g_cf + ((size_t)bb * 256 + tid) * 128;
                float a0 = 0.f, a1 = 0.f, a2 = 0.f, a3 = 0.f;
                for (int j = 0; j < 128; j += 4) {
                    a0 += sh_q[j + 0] * cfp[j + 0];
                    a1 += sh_q[j + 1] * cfp[j + 1];
                    a2 += sh_q[j + 2] * cfp[j + 2];
                    a3 += sh_q[j + 3] * cfp[j + 3];
                }
                sh_e[tid] = a0 + a1 + a2 + a3;
            }
            __syncthreads();

            float v = sh_e[tid];
            sr[tid] = v; __syncthreads();
            for (int s = 128; s > 0; s >>= 1) { if (tid < s) sr[tid] = fmaxf(sr[tid], sr[tid + s]); __syncthreads(); }
            float m = sr[0]; __syncthreads();
            float e = expf(v - m);
            sr[tid] = e; __syncthreads();
            for (int s = 128; s > 0; s >>= 1) { if (tid < s) sr[tid] += sr[tid + s]; __syncthreads(); }
            float inv = 1.f / sr[0];
            __syncthreads();
            sh_e[tid] = e * inv;
            __syncthreads();

            for (int d0 = 0; d0 < 512; d0 += 256) {
                int d = d0 + tid;
                const float* fp = g_feats + (size_t)bb * 256 * 512 + d;
                float a0 = 0.f, a1 = 0.f, a2 = 0.f, a3 = 0.f;
                for (int tt2 = 0; tt2 < 256; tt2 += 4) {
                    a0 += sh_e[tt2 + 0] * fp[(size_t)(tt2 + 0) * 512];
                    a1 += sh_e[tt2 + 1] * fp[(size_t)(tt2 + 1) * 512];
                    a2 += sh_e[tt2 + 2] * fp[(size_t)(tt2 + 2) * 512];
                    a3 += sh_e[tt2 + 3] * fp[(size_t)(tt2 + 3) * 512];
                }
                float cv = a0 + a1 + a2 + a3;
                sh_c2[d] = cv;
                __stcg(&g_ctx[(size_t)bb * 512 + d], cv);
            }
            __syncthreads();

            if (tid < 48) {
                const float* wr = fcW + (size_t)tid * 1024;
                float a0 = 0.f, a1 = 0.f;
                for (int k = 0; k < 512; k++) {
                    a0 += sh_h[k] * wr[k];
                    a1 += sh_c2[k] * wr[512 + k];
                }
                sh_l[tid] = a0 + a1 + fcb[tid];
            }
            __syncthreads();
            if (tid < 48) {
                float m2 = -1e30f;
                for (int j = 0; j < 48; j++) m2 = fmaxf(m2, sh_l[j]);
                float s2 = 0.f;
                for (int j = 0; j < 48; j++) s2 += expf(sh_l[j] - m2);
                out_lps[(size_t)bb * TDEC * NVOC + (size_t)t * NVOC + tid] = sh_l[tid] - m2 - logf(s2);
            }
        }
        gbar(ctr, epoch, nb);
    }
}

// ---------------- small helpers ----------------
__global__ void transpose_phi(const float* __restrict__ W) {
    int j = blockIdx.x;
    for (int k = threadIdx.x; k < 512; k += 256) g_phiWt[k * 128 + j] = W[j * 512 + k];
}

__global__ void fin_hc(float* __restrict__ out) {
    int b = blockIdx.x;
    for (int i = threadIdx.x; i < 1024; i += 256) {
        int q = i >> 8, r = i & 255;
        float v;
        if (q == 0)      v = g_h[(size_t)(0 * 2 + 0) * 64 * 256 + b * 256 + r];
        else if (q == 1) v = g_h[(size_t)(0 * 2 + 1) * 64 * 256 + b * 256 + r];
        else if (q == 2) v = g_c[(size_t)(0 * 64 + b) * 256 + r];
        else             v = g_c[(size_t)(1 * 64 + b) * 256 + r];
        out[(size_t)b * 1024 + i] = v;
    }
}

// ---------------- host launcher ----------------
extern "C" void kernel_launch(void* const* d_in, const int* in_sizes, int n_in,
                              void* d_out, int out_size)
{
    const float* inputs = (const float*)d_in[0];
    const int*   gt     = (const int*)d_in[1];
    const float* W[27];
    for (int i = 0; i < 27; i++) W[i] = (const float*)d_in[i + 2];

    float *xw0, *xw1, *out0, *out1, *feats, *cf;
    unsigned *barE, *barD;
    cudaGetSymbolAddress((void**)&xw0, g_xw0);
    cudaGetSymbolAddress((void**)&xw1, g_xw1);
    cudaGetSymbolAddress((void**)&out0, g_out0);
    cudaGetSymbolAddress((void**)&out1, g_out1);
    cudaGetSymbolAddress((void**)&feats, g_feats);
    cudaGetSymbolAddress((void**)&cf, g_cf);
    cudaGetSymbolAddress((void**)&barE, g_barE);
    cudaGetSymbolAddress((void**)&barD, g_barD);

    cudaFuncSetAttribute(enc_scan, cudaFuncAttributeMaxDynamicSharedMemorySize, ENC_SMEM);
    cudaFuncSetAttribute(dec_scan, cudaFuncAttributeMaxDynamicSharedMemorySize, DEC_SMEM);

    float* dout = (float*)d_out;

    // ---------------- encoder ----------------
    const float* A = inputs;
    float* outs[3] = {out0, out1, feats};
    int Tl = 1024, K = 160;
    for (int l = 0; l < 3; l++) {
        int M = 64 * Tl;
        dim3 gg(1024 / 128, M / 128);
        gemm_bias<<<gg, 256>>>(A, W[l * 6 + 0], W[l * 6 + 2], xw0, M, 1024, K, 0);
        gemm_bias<<<gg, 256>>>(A, W[l * 6 + 3], W[l * 6 + 5], xw1, M, 1024, K, 0);
        cudaMemsetAsync(barE, 0, 8);
        enc_scan<<<dim3(64, 2), 256, ENC_SMEM>>>(xw0, xw1, W[l * 6 + 1], W[l * 6 + 4], outs[l], Tl);
        A = outs[l];
        Tl >>= 1;
        K = 1024;
    }

    // comp_feat = relu(feats @ psi_W^T + psi_b)   [16384,128]
    gemm_bias<<<dim3(1, 16384 / 128), 256>>>(feats, W[23], W[24], cf, 16384, 128, 512, 1);
    transpose_phi<<<128, 256>>>(W[21]);
    fin_hc<<<64, 256>>>(dout + (size_t)BATCH * TDEC * NVOC);

    // ---------------- decoder ----------------
    cudaMemsetAsync(barD, 0, 4);
    dec_scan<<<128, 256, DEC_SMEM>>>(W[18], W[19], W[20], gt, W[22], W[25], W[26], dout);
}

// round 4
// speedup vs baseline: 1.0112x; 1.0112x over previous
#include <cuda_runtime.h>
#include <math.h>

// ---------------- problem constants ----------------
#define BATCH 64
#define TDEC  150
#define NVOC  48
#define LHID  256
#define SHID  512
#define NMLP  128

typedef unsigned long long ull;

// ---------------- device scratch ----------------
__device__ float g_xw0[64*1024*1024];
__device__ float g_xw1[64*1024*1024];
__device__ float g_out0[64*1024*512];
__device__ float g_out1[64*512*512];
__device__ float g_feats[64*256*512];
__device__ float g_cf[64*256*128];
__device__ float g_h[2*2*64*256];          // [parity][dir][b][256]
__device__ float g_c[2*64*256];
__device__ float g_dh[2*64*512];
__device__ float g_ctx[64*512];
__device__ float g_phiWt[512*128];
__device__ unsigned g_barE[2];             // per-direction encoder barriers
__device__ unsigned g_barD;                // decoder barrier

// ---------------- software grid barrier (release/acquire, no L1 flush) -----
__device__ __forceinline__ void gbar(unsigned* ctr, unsigned& epoch, unsigned nb)
{
    __syncthreads();
    if (threadIdx.x == 0) {
        unsigned target = epoch + nb;
        asm volatile("red.release.gpu.global.add.u32 [%0], %1;"
                     :: "l"(ctr), "r"(1u) : "memory");
        unsigned v;
        do {
            asm volatile("ld.acquire.gpu.global.u32 %0, [%1];"
                         : "=r"(v) : "l"(ctr) : "memory");
        } while (v < target);
    }
    epoch += nb;
    __syncthreads();
}

// ---------------- packed fp32x2 FMA (SASS FFMA2) ----------------
__device__ __forceinline__ void fma2(ull& d, ull a, ull b)
{
    asm("fma.rn.f32x2 %0, %1, %2, %0;" : "+l"(d) : "l"(a), "l"(b));
}

union UP { float4 f; ull u[2]; };
union U2 { ull u; float2 f; };

// ---------------- fp32 GEMM via f32x2: C[M,N] = A@W^T + bias, opt relu ------
// Tile 128(M) x 64(N), BK=16, 256 threads (16x16), 8 rows x 4 cols (2 ull) per
// thread. A duplicated in smem so the broadcast operand is a native 64-bit LDS.
// Requires M%128==0, N%64==0, K%16==0 (true at all call sites).
__global__ __launch_bounds__(256, 3) void gemm_bias(
    const float* __restrict__ A, const float* __restrict__ W,
    const float* __restrict__ bias, float* __restrict__ C,
    int M, int N, int K, int relu)
{
    __shared__ float As2[16 * 264];   // As2[k][2m] = As2[k][2m+1] = A[m][k]
    __shared__ float Ws[16 * 68];     // Ws[k][n]
    int bm = blockIdx.y << 7, bn = blockIdx.x << 6;
    int tid = threadIdx.x;
    int ty = tid >> 4, tx = tid & 15;
    const float* Ap = A + (size_t)bm * K;
    const float* Wp = W + (size_t)bn * K;

    ull acc[8][2];
#pragma unroll
    for (int i = 0; i < 8; i++) { acc[i][0] = 0ull; acc[i][1] = 0ull; }

    for (int k0 = 0; k0 < K; k0 += 16) {
#pragma unroll
        for (int j = 0; j < 2; j++) {
            int idx = tid + 256 * j;
            int r = idx >> 2, c = (idx & 3) << 2;
            float4 v = *(const float4*)&Ap[(size_t)r * K + k0 + c];
            *(float2*)&As2[(c + 0) * 264 + 2 * r] = make_float2(v.x, v.x);
            *(float2*)&As2[(c + 1) * 264 + 2 * r] = make_float2(v.y, v.y);
            *(float2*)&As2[(c + 2) * 264 + 2 * r] = make_float2(v.z, v.z);
            *(float2*)&As2[(c + 3) * 264 + 2 * r] = make_float2(v.w, v.w);
        }
        {
            int r = tid >> 2, c = (tid & 3) << 2;
            float4 v = *(const float4*)&Wp[(size_t)r * K + k0 + c];
            Ws[(c + 0) * 68 + r] = v.x;
            Ws[(c + 1) * 68 + r] = v.y;
            Ws[(c + 2) * 68 + r] = v.z;
            Ws[(c + 3) * 68 + r] = v.w;
        }
        __syncthreads();
#pragma unroll
        for (int kk = 0; kk < 16; kk++) {
            UP a0, a1, a2, a3, w;
            a0.f = *(const float4*)&As2[kk * 264 + ty * 16 + 0];
            a1.f = *(const float4*)&As2[kk * 264 + ty * 16 + 4];
            a2.f = *(const float4*)&As2[kk * 264 + ty * 16 + 8];
            a3.f = *(const float4*)&As2[kk * 264 + ty * 16 + 12];
            w.f  = *(const float4*)&Ws[kk * 68 + tx * 4];
            fma2(acc[0][0], a0.u[0], w.u[0]); fma2(acc[0][1], a0.u[0], w.u[1]);
            fma2(acc[1][0], a0.u[1], w.u[0]); fma2(acc[1][1], a0.u[1], w.u[1]);
            fma2(acc[2][0], a1.u[0], w.u[0]); fma2(acc[2][1], a1.u[0], w.u[1]);
            fma2(acc[3][0], a1.u[1], w.u[0]); fma2(acc[3][1], a1.u[1], w.u[1]);
            fma2(acc[4][0], a2.u[0], w.u[0]); fma2(acc[4][1], a2.u[0], w.u[1]);
            fma2(acc[5][0], a2.u[1], w.u[0]); fma2(acc[5][1], a2.u[1], w.u[1]);
            fma2(acc[6][0], a3.u[0], w.u[0]); fma2(acc[6][1], a3.u[0], w.u[1]);
            fma2(acc[7][0], a3.u[1], w.u[0]); fma2(acc[7][1], a3.u[1], w.u[1]);
        }
        __syncthreads();
    }
    float4 bv = *(const float4*)&bias[bn + tx * 4];
#pragma unroll
    for (int i = 0; i < 8; i++) {
        int m = bm + ty * 8 + i;
        U2 p0, p1;
        p0.u = acc[i][0]; p1.u = acc[i][1];
        float4 o;
        o.x = p0.f.x + bv.x; o.y = p0.f.y + bv.y;
        o.z = p1.f.x + bv.z; o.w = p1.f.y + bv.w;
        if (relu) {
            o.x = fmaxf(o.x, 0.f); o.y = fmaxf(o.y, 0.f);
            o.z = fmaxf(o.z, 0.f); o.w = fmaxf(o.w, 0.f);
        }
        *(float4*)&C[(size_t)m * N + bn + tx * 4] = o;
    }
}

// ---------------- persistent encoder scan (per-direction barrier) -----------
#define ENC_SMEM ((16 * 264 + 64 * 260) * 4)
__global__ __launch_bounds__(256) void enc_scan(
    const float* __restrict__ xw_f, const float* __restrict__ xw_b,
    const float* __restrict__ whh_f, const float* __restrict__ whh_b,
    float* __restrict__ out, int Tl)
{
    extern __shared__ float smem[];
    float* sh_w = smem;               // 16 x 256 (pitch 264)
    float* sh_x = smem + 16 * 264;    // 64 x 256 (pitch 260)

    int tid = threadIdx.x;
    int lane = tid & 31, wrp = tid >> 5;
    int u = wrp & 3, bh = wrp >> 2;
    int b = bh * 32 + lane;
    int dir = blockIdx.y;
    int hu0 = blockIdx.x << 2;
    int hu = hu0 + u;
    unsigned epoch = 0;
    const unsigned nb = gridDim.x;       // 64 blocks per direction
    unsigned* ctr = &g_barE[dir];

    const float* xw  = dir ? xw_b  : xw_f;
    const float* Whh = dir ? whh_b : whh_f;

    for (int i = tid; i < 16 * 64; i += 256) {
        int r = i >> 6, kq = (i & 63) << 2;
        int grow = ((r >> 2) << 8) + hu0 + (r & 3);
        *(float4*)&sh_w[r * 264 + kq] = *(const float4*)&Whh[(size_t)grow * 256 + kq];
    }

    float creg = 0.f;
    __stcg(&g_h[(size_t)(0 * 2 + dir) * 64 * 256 + b * 256 + hu], 0.f);
    gbar(ctr, epoch, nb);

    for (int t = 0; t < Tl; t++) {
        int tt = dir ? (Tl - 1 - t) : t;
        int pin = t & 1, pout = pin ^ 1;
        const float* hin = g_h + (size_t)(pin * 2 + dir) * 64 * 256;

        // prefetch gate pre-activations (strided DRAM gather) early
        size_t xi = ((size_t)b * Tl + tt) * 1024 + hu;
        float x0 = __ldg(&xw[xi]);
        float x1 = __ldg(&xw[xi + 256]);
        float x2 = __ldg(&xw[xi + 512]);
        float x3 = __ldg(&xw[xi + 768]);

        __syncthreads();
        for (int i = tid; i < 64 * 64; i += 256) {
            int bb = i >> 6, kq = (i & 63) << 2;
            *(float4*)&sh_x[bb * 260 + kq] = __ldcg((const float4*)&hin[bb * 256 + kq]);
        }
        __syncthreads();

        float acc0 = 0.f, acc1 = 0.f, acc2 = 0.f, acc3 = 0.f;
#pragma unroll 8
        for (int kk = 0; kk < 256; kk += 4) {
            float4 hv = *(const float4*)&sh_x[b * 260 + kk];
            float4 w0 = *(const float4*)&sh_w[(0 * 4 + u) * 264 + kk];
            float4 w1 = *(const float4*)&sh_w[(1 * 4 + u) * 264 + kk];
            float4 w2 = *(const float4*)&sh_w[(2 * 4 + u) * 264 + kk];
            float4 w3 = *(const float4*)&sh_w[(3 * 4 + u) * 264 + kk];
            acc0 += hv.x * w0.x + hv.y * w0.y + hv.z * w0.z + hv.w * w0.w;
            acc1 += hv.x * w1.x + hv.y * w1.y + hv.z * w1.z + hv.w * w1.w;
            acc2 += hv.x * w2.x + hv.y * w2.y + hv.z * w2.z + hv.w * w2.w;
            acc3 += hv.x * w3.x + hv.y * w3.y + hv.z * w3.z + hv.w * w3.w;
        }
        float zi = acc0 + x0;
        float zf = acc1 + x1;
        float zg = acc2 + x2;
        float zo = acc3 + x3;
        float si = 1.f / (1.f + expf(-zi));
        float sf = 1.f / (1.f + expf(-zf));
        float so = 1.f / (1.f + expf(-zo));
        float cn = sf * creg + si * tanhf(zg);
        float hn = so * tanhf(cn);
        creg = cn;
        __stcg(&g_h[(size_t)(pout * 2 + dir) * 64 * 256 + b * 256 + hu], hn);
        out[((size_t)b * Tl + tt) * 512 + dir * 256 + hu] = hn;
        gbar(ctr, epoch, nb);
    }
    g_c[(size_t)(dir * 64 + b) * 256 + hu] = creg;
}

// ---------------- persistent decoder (LSTM step + attention fused) ----------
#define DEC_SMEM ((16 * 1032 + 64 * 132 + 512 + 128 + 256 + 512 + 64 + 256) * 4)
__global__ __launch_bounds__(256) void dec_scan(
    const float* __restrict__ sWih, const float* __restrict__ sWhh,
    const float* __restrict__ sb, const int* __restrict__ gt,
    const float* __restrict__ phi_b,
    const float* __restrict__ fcW, const float* __restrict__ fcb,
    float* __restrict__ out_lps)
{
    extern __shared__ float smem[];
    float* sh_w  = smem;
    float* sh_x  = sh_w + 16 * 1032;
    float* sh_h  = sh_x + 64 * 132;
    float* sh_q  = sh_h + 512;
    float* sh_e  = sh_q + 128;
    float* sh_c2 = sh_e + 256;
    float* sh_l  = sh_c2 + 512;
    float* sr    = sh_l + 64;

    int tid = threadIdx.x;
    int lane = tid & 31, wrp = tid >> 5;
    int u = wrp & 3, bh = wrp >> 2;
    int b = bh * 32 + lane;
    int hu0 = blockIdx.x << 2;
    int hu = hu0 + u;
    unsigned epoch = 0;
    const unsigned nb = gridDim.x;
    unsigned* ctr = &g_barD;

    for (int i = tid; i < 16 * 256; i += 256) {
        int r = i >> 8, kq = (i & 255) << 2;
        int grow = (r >> 2) * SHID + hu0 + (r & 3);
        float4 v;
        if (kq < 512) v = *(const float4*)&sWih[(size_t)grow * 560 + 48 + kq];
        else          v = *(const float4*)&sWhh[(size_t)grow * 512 + (kq - 512)];
        *(float4*)&sh_w[r * 1032 + kq] = v;
    }

    float creg = 0.f;
    __stcg(&g_dh[(size_t)b * 512 + hu], 0.f);
    __stcg(&g_ctx[(size_t)b * 512 + hu], __ldg(&g_feats[(size_t)b * 256 * 512 + hu]));
    gbar(ctr, epoch, nb);

    float bi0 = sb[0 * SHID + hu], bi1 = sb[1 * SHID + hu];
    float bi2 = sb[2 * SHID + hu], bi3 = sb[3 * SHID + hu];

    for (int t = 0; t < TDEC; t++) {
        int pin = t & 1, pout = pin ^ 1;
        int tok = (t == 0) ? 0 : gt[b * TDEC + (t - 1)];
        float acc0 = sWih[(size_t)(0 * SHID + hu) * 560 + tok] + bi0;
        float acc1 = sWih[(size_t)(1 * SHID + hu) * 560 + tok] + bi1;
        float acc2 = sWih[(size_t)(2 * SHID + hu) * 560 + tok] + bi2;
        float acc3 = sWih[(size_t)(3 * SHID + hu) * 560 + tok] + bi3;

        const float* hin = g_dh + (size_t)pin * 64 * 512;
        for (int c = 0; c < 8; c++) {
            __syncthreads();
            const float* src = (c < 4) ? (g_ctx + (c << 7)) : (hin + ((c - 4) << 7));
            for (int i = tid; i < 64 * 32; i += 256) {
                int bb = i >> 5, kq = (i & 31) << 2;
                *(float4*)&sh_x[bb * 132 + kq] = __ldcg((const float4*)&src[(size_t)bb * 512 + kq]);
            }
            __syncthreads();
            const float* wp = sh_w + c * 128;
#pragma unroll 8
            for (int kk = 0; kk < 128; kk += 4) {
                float4 hv = *(const float4*)&sh_x[b * 132 + kk];
                float4 w0 = *(const float4*)&wp[(0 * 4 + u) * 1032 + kk];
                float4 w1 = *(const float4*)&wp[(1 * 4 + u) * 1032 + kk];
                float4 w2 = *(const float4*)&wp[(2 * 4 + u) * 1032 + kk];
                float4 w3 = *(const float4*)&wp[(3 * 4 + u) * 1032 + kk];
                acc0 += hv.x * w0.x + hv.y * w0.y + hv.z * w0.z + hv.w * w0.w;
                acc1 += hv.x * w1.x + hv.y * w1.y + hv.z * w1.z + hv.w * w1.w;
                acc2 += hv.x * w2.x + hv.y * w2.y + hv.z * w2.z + hv.w * w2.w;
                acc3 += hv.x * w3.x + hv.y * w3.y + hv.z * w3.z + hv.w * w3.w;
            }
        }
        float si = 1.f / (1.f + expf(-acc0));
        float sf = 1.f / (1.f + expf(-acc1));
        float so = 1.f / (1.f + expf(-acc3));
        float cn = sf * creg + si * tanhf(acc2);
        float hn = so * tanhf(cn);
        creg = cn;
        __stcg(&g_dh[(size_t)pout * 64 * 512 + b * 512 + hu], hn);
        gbar(ctr, epoch, nb);

        if (blockIdx.x < 64) {
            int bb = blockIdx.x;
            const float* h = g_dh + (size_t)pout * 64 * 512 + (size_t)bb * 512;
            for (int i = tid; i < 512; i += 256) sh_h[i] = __ldcg(&h[i]);
            __syncthreads();

            if (tid < 128) {
                float a0 = 0.f, a1 = 0.f, a2 = 0.f, a3 = 0.f;
                for (int k = 0; k < 512; k += 4) {
                    a0 += sh_h[k + 0] * g_phiWt[(k + 0) * 128 + tid];
                    a1 += sh_h[k + 1] * g_phiWt[(k + 1) * 128 + tid];
                    a2 += sh_h[k + 2] * g_phiWt[(k + 2) * 128 + tid];
                    a3 += sh_h[k + 3] * g_phiWt[(k + 3) * 128 + tid];
                }
                float q = a0 + a1 + a2 + a3 + phi_b[tid];
                sh_q[tid] = q > 0.f ? q : 0.f;
            }
            __syncthreads();

            {
                const float* cfp = g_cf + ((size_t)bb * 256 + tid) * 128;
                float a0 = 0.f, a1 = 0.f, a2 = 0.f, a3 = 0.f;
                for (int j = 0; j < 128; j += 4) {
                    a0 += sh_q[j + 0] * cfp[j + 0];
                    a1 += sh_q[j + 1] * cfp[j + 1];
                    a2 += sh_q[j + 2] * cfp[j + 2];
                    a3 += sh_q[j + 3] * cfp[j + 3];
                }
                sh_e[tid] = a0 + a1 + a2 + a3;
            }
            __syncthreads();

            float v = sh_e[tid];
            sr[tid] = v; __syncthreads();
            for (int s = 128; s > 0; s >>= 1) { if (tid < s) sr[tid] = fmaxf(sr[tid], sr[tid + s]); __syncthreads(); }
            float m = sr[0]; __syncthreads();
            float e = expf(v - m);
            sr[tid] = e; __syncthreads();
            for (int s = 128; s > 0; s >>= 1) { if (tid < s) sr[tid] += sr[tid + s]; __syncthreads(); }
            float inv = 1.f / sr[0];
            __syncthreads();
            sh_e[tid] = e * inv;
            __syncthreads();

            for (int d0 = 0; d0 < 512; d0 += 256) {
                int d = d0 + tid;
                const float* fp = g_feats + (size_t)bb * 256 * 512 + d;
                float a0 = 0.f, a1 = 0.f, a2 = 0.f, a3 = 0.f;
                for (int tt2 = 0; tt2 < 256; tt2 += 4) {
                    a0 += sh_e[tt2 + 0] * fp[(size_t)(tt2 + 0) * 512];
                    a1 += sh_e[tt2 + 1] * fp[(size_t)(tt2 + 1) * 512];
                    a2 += sh_e[tt2 + 2] * fp[(size_t)(tt2 + 2) * 512];
                    a3 += sh_e[tt2 + 3] * fp[(size_t)(tt2 + 3) * 512];
                }
                float cv = a0 + a1 + a2 + a3;
                sh_c2[d] = cv;
                __stcg(&g_ctx[(size_t)bb * 512 + d], cv);
            }
            __syncthreads();

            if (tid < 48) {
                const float* wr = fcW + (size_t)tid * 1024;
                float a0 = 0.f, a1 = 0.f;
                for (int k = 0; k < 512; k++) {
                    a0 += sh_h[k] * wr[k];
                    a1 += sh_c2[k] * wr[512 + k];
                }
                sh_l[tid] = a0 + a1 + fcb[tid];
            }
            __syncthreads();
            if (tid < 48) {
                float m2 = -1e30f;
                for (int j = 0; j < 48; j++) m2 = fmaxf(m2, sh_l[j]);
                float s2 = 0.f;
                for (int j = 0; j < 48; j++) s2 += expf(sh_l[j] - m2);
                out_lps[(size_t)bb * TDEC * NVOC + (size_t)t * NVOC + tid] = sh_l[tid] - m2 - logf(s2);
            }
        }
        gbar(ctr, epoch, nb);
    }
}

// ---------------- small helpers ----------------
__global__ void transpose_phi(const float* __restrict__ W) {
    int j = blockIdx.x;
    for (int k = threadIdx.x; k < 512; k += 256) g_phiWt[k * 128 + j] = W[j * 512 + k];
}

__global__ void fin_hc(float* __restrict__ out) {
    int b = blockIdx.x;
    for (int i = threadIdx.x; i < 1024; i += 256) {
        int q = i >> 8, r = i & 255;
        float v;
        if (q == 0)      v = g_h[(size_t)(0 * 2 + 0) * 64 * 256 + b * 256 + r];
        else if (q == 1) v = g_h[(size_t)(0 * 2 + 1) * 64 * 256 + b * 256 + r];
        else if (q == 2) v = g_c[(size_t)(0 * 64 + b) * 256 + r];
        else             v = g_c[(size_t)(1 * 64 + b) * 256 + r];
        out[(size_t)b * 1024 + i] = v;
    }
}

// ---------------- host launcher ----------------
extern "C" void kernel_launch(void* const* d_in, const int* in_sizes, int n_in,
                              void* d_out, int out_size)
{
    const float* inputs = (const float*)d_in[0];
    const int*   gt     = (const int*)d_in[1];
    const float* W[27];
    for (int i = 0; i < 27; i++) W[i] = (const float*)d_in[i + 2];

    float *xw0, *xw1, *out0, *out1, *feats, *cf;
    unsigned *barE, *barD;
    cudaGetSymbolAddress((void**)&xw0, g_xw0);
    cudaGetSymbolAddress((void**)&xw1, g_xw1);
    cudaGetSymbolAddress((void**)&out0, g_out0);
    cudaGetSymbolAddress((void**)&out1, g_out1);
    cudaGetSymbolAddress((void**)&feats, g_feats);
    cudaGetSymbolAddress((void**)&cf, g_cf);
    cudaGetSymbolAddress((void**)&barE, g_barE);
    cudaGetSymbolAddress((void**)&barD, g_barD);

    cudaFuncSetAttribute(enc_scan, cudaFuncAttributeMaxDynamicSharedMemorySize, ENC_SMEM);
    cudaFuncSetAttribute(dec_scan, cudaFuncAttributeMaxDynamicSharedMemorySize, DEC_SMEM);

    float* dout = (float*)d_out;

    // ---------------- encoder ----------------
    const float* A = inputs;
    float* outs[3] = {out0, out1, feats};
    int Tl = 1024, K = 160;
    for (int l = 0; l < 3; l++) {
        int M = 64 * Tl;
        dim3 gg(1024 / 64, M / 128);
        gemm_bias<<<gg, 256>>>(A, W[l * 6 + 0], W[l * 6 + 2], xw0, M, 1024, K, 0);
        gemm_bias<<<gg, 256>>>(A, W[l * 6 + 3], W[l * 6 + 5], xw1, M, 1024, K, 0);
        cudaMemsetAsync(barE, 0, 8);
        enc_scan<<<dim3(64, 2), 256, ENC_SMEM>>>(xw0, xw1, W[l * 6 + 1], W[l * 6 + 4], outs[l], Tl);
        A = outs[l];
        Tl >>= 1;
        K = 1024;
    }

    // comp_feat = relu(feats @ psi_W^T + psi_b)   [16384,128]
    gemm_bias<<<dim3(2, 16384 / 128), 256>>>(feats, W[23], W[24], cf, 16384, 128, 512, 1);
    transpose_phi<<<128, 256>>>(W[21]);
    fin_hc<<<64, 256>>>(dout + (size_t)BATCH * TDEC * NVOC);

    // ---------------- decoder ----------------
    cudaMemsetAsync(barD, 0, 4);
    dec_scan<<<128, 256, DEC_SMEM>>>(W[18], W[19], W[20], gt, W[22], W[25], W[26], dout);
}

// round 5
// speedup vs baseline: 1.0854x; 1.0734x over previous
#include <cuda_runtime.h>
#include <math.h>

// ---------------- problem constants ----------------
#define BATCH 64
#define TDEC  150
#define NVOC  48
#define LHID  256
#define SHID  512
#define NMLP  128

typedef unsigned long long ull;

// ---------------- device scratch ----------------
__device__ float g_xw0[64*1024*1024];
__device__ float g_xw1[64*1024*1024];
__device__ float g_out0[64*1024*512];
__device__ float g_out1[64*512*512];
__device__ float g_feats[64*256*512];
__device__ float g_cf[64*256*128];
__device__ float g_h[2*2*64*256];          // [parity][dir][b][256]
__device__ float g_c[2*64*256];
__device__ float g_dh[2*64*512];
__device__ float g_ctx[64*512];
__device__ float g_phiWt[512*128];
__device__ unsigned g_barE[2];             // per-direction encoder barriers
__device__ unsigned g_barD;                // decoder barrier

// ---------------- software grid barrier (release/acquire) ----------------
__device__ __forceinline__ void gbar(unsigned* ctr, unsigned& epoch, unsigned nb)
{
    __syncthreads();
    if (threadIdx.x == 0) {
        unsigned target = epoch + nb;
        asm volatile("red.release.gpu.global.add.u32 [%0], %1;"
                     :: "l"(ctr), "r"(1u) : "memory");
        unsigned v;
        do {
            asm volatile("ld.acquire.gpu.global.u32 %0, [%1];"
                         : "=r"(v) : "l"(ctr) : "memory");
        } while (v < target);
    }
    epoch += nb;
    __syncthreads();
}

// ---------------- packed fp32x2 FMA (SASS FFMA2) ----------------
__device__ __forceinline__ void fma2(ull& d, ull a, ull b)
{
    asm("fma.rn.f32x2 %0, %1, %2, %0;" : "+l"(d) : "l"(a), "l"(b));
}

union UP { float4 f; ull u[2]; };
union U2 { ull u; float2 f; };

// ---------------- barrier reset + pad launches (profiling alignment) -------
__global__ void reset_bars() {
    if (threadIdx.x == 0 && blockIdx.x == 0) {
        g_barE[0] = 0; g_barE[1] = 0; g_barD = 0;
    }
}
__global__ void nop_kernel() {}

// ---------------- fp32 GEMM (R2-proven tile): C = A@W^T + bias -------------
// Tile 128(M) x 64(N), BK=16, 256 threads, 8x4 per thread.
// gate_perm: output column n' maps to weight/bias row (n'&3)*256 + (n'>>2)
// so C comes out gate-interleaved: n' = hu*4 + gate.
__global__ __launch_bounds__(256) void gemm_bias(
    const float* __restrict__ A, const float* __restrict__ W,
    const float* __restrict__ bias, float* __restrict__ C,
    int M, int N, int K, int relu, int gate_perm)
{
    __shared__ float As[16 * 132];
    __shared__ float Ws[16 * 68];
    int bm = blockIdx.y << 7, bn = blockIdx.x << 6;
    int tid = threadIdx.x;
    int ty = tid >> 4, tx = tid & 15;
    const float* Ap = A + (size_t)bm * K;

    // fixed per-thread W row (with optional gate permutation)
    int wr = tid >> 2, wc = (tid & 3) << 2;
    int nprime = bn + wr;
    int nrow = gate_perm ? ((nprime & 3) * 256 + (nprime >> 2)) : nprime;
    const float* WpRow = W + (size_t)nrow * K;

    float acc[8][4];
#pragma unroll
    for (int i = 0; i < 8; i++)
#pragma unroll
        for (int j = 0; j < 4; j++) acc[i][j] = 0.f;

    for (int k0 = 0; k0 < K; k0 += 16) {
#pragma unroll
        for (int j = 0; j < 2; j++) {
            int idx = tid + 256 * j;
            int r = idx >> 2, c = (idx & 3) << 2;
            float4 v = *(const float4*)&Ap[(size_t)r * K + k0 + c];
            As[(c + 0) * 132 + r] = v.x;
            As[(c + 1) * 132 + r] = v.y;
            As[(c + 2) * 132 + r] = v.z;
            As[(c + 3) * 132 + r] = v.w;
        }
        {
            float4 v = *(const float4*)&WpRow[k0 + wc];
            Ws[(wc + 0) * 68 + wr] = v.x;
            Ws[(wc + 1) * 68 + wr] = v.y;
            Ws[(wc + 2) * 68 + wr] = v.z;
            Ws[(wc + 3) * 68 + wr] = v.w;
        }
        __syncthreads();
#pragma unroll
        for (int kk = 0; kk < 16; kk++) {
            float4 a0 = *(const float4*)&As[kk * 132 + ty * 8];
            float4 a1 = *(const float4*)&As[kk * 132 + ty * 8 + 4];
            float4 w  = *(const float4*)&Ws[kk * 68 + tx * 4];
            acc[0][0] += a0.x * w.x; acc[0][1] += a0.x * w.y; acc[0][2] += a0.x * w.z; acc[0][3] += a0.x * w.w;
            acc[1][0] += a0.y * w.x; acc[1][1] += a0.y * w.y; acc[1][2] += a0.y * w.z; acc[1][3] += a0.y * w.w;
            acc[2][0] += a0.z * w.x; acc[2][1] += a0.z * w.y; acc[2][2] += a0.z * w.z; acc[2][3] += a0.z * w.w;
            acc[3][0] += a0.w * w.x; acc[3][1] += a0.w * w.y; acc[3][2] += a0.w * w.z; acc[3][3] += a0.w * w.w;
            acc[4][0] += a1.x * w.x; acc[4][1] += a1.x * w.y; acc[4][2] += a1.x * w.z; acc[4][3] += a1.x * w.w;
            acc[5][0] += a1.y * w.x; acc[5][1] += a1.y * w.y; acc[5][2] += a1.y * w.z; acc[5][3] += a1.y * w.w;
            acc[6][0] += a1.z * w.x; acc[6][1] += a1.z * w.y; acc[6][2] += a1.z * w.z; acc[6][3] += a1.z * w.w;
            acc[7][0] += a1.w * w.x; acc[7][1] += a1.w * w.y; acc[7][2] += a1.w * w.z; acc[7][3] += a1.w * w.w;
        }
        __syncthreads();
    }
    float bvx, bvy, bvz, bvw;
    if (gate_perm) {
        int n0 = bn + tx * 4;
        bvx = bias[((n0 + 0) & 3) * 256 + ((n0 + 0) >> 2)];
        bvy = bias[((n0 + 1) & 3) * 256 + ((n0 + 1) >> 2)];
        bvz = bias[((n0 + 2) & 3) * 256 + ((n0 + 2) >> 2)];
        bvw = bias[((n0 + 3) & 3) * 256 + ((n0 + 3) >> 2)];
    } else {
        float4 bv = *(const float4*)&bias[bn + tx * 4];
        bvx = bv.x; bvy = bv.y; bvz = bv.z; bvw = bv.w;
    }
#pragma unroll
    for (int i = 0; i < 8; i++) {
        int m = bm + ty * 8 + i;
        float4 o;
        o.x = acc[i][0] + bvx; o.y = acc[i][1] + bvy;
        o.z = acc[i][2] + bvz; o.w = acc[i][3] + bvw;
        if (relu) {
            o.x = fmaxf(o.x, 0.f); o.y = fmaxf(o.y, 0.f);
            o.z = fmaxf(o.z, 0.f); o.w = fmaxf(o.w, 0.f);
        }
        *(float4*)&C[(size_t)m * N + bn + tx * 4] = o;
    }
}

// ---------------- persistent encoder scan ----------------
// xw is gate-interleaved: xw[(b*Tl+t)*1024 + hu*4 + gate]
#define ENC_SMEM ((16 * 264 + 64 * 260) * 4)
__global__ __launch_bounds__(256) void enc_scan(
    const float* __restrict__ xw_f, const float* __restrict__ xw_b,
    const float* __restrict__ whh_f, const float* __restrict__ whh_b,
    float* __restrict__ out, int Tl, unsigned epoch0)
{
    extern __shared__ float smem[];
    float* sh_w = smem;               // 16 x 256 (pitch 264)
    float* sh_x = smem + 16 * 264;    // 64 x 256 (pitch 260)

    int tid = threadIdx.x;
    int lane = tid & 31, wrp = tid >> 5;
    int u = wrp & 3, bh = wrp >> 2;
    int b = bh * 32 + lane;
    int dir = blockIdx.y;
    int hu0 = blockIdx.x << 2;
    int hu = hu0 + u;
    unsigned epoch = epoch0;
    const unsigned nb = gridDim.x;       // 64 blocks per direction
    unsigned* ctr = &g_barE[dir];

    const float* xw  = dir ? xw_b  : xw_f;
    const float* Whh = dir ? whh_b : whh_f;

    for (int i = tid; i < 16 * 64; i += 256) {
        int r = i >> 6, kq = (i & 63) << 2;
        int grow = ((r >> 2) << 8) + hu0 + (r & 3);
        *(float4*)&sh_w[r * 264 + kq] = *(const float4*)&Whh[(size_t)grow * 256 + kq];
    }

    float creg = 0.f;
    __stcg(&g_h[(size_t)(0 * 2 + dir) * 64 * 256 + b * 256 + hu], 0.f);
    gbar(ctr, epoch, nb);

    for (int t = 0; t < Tl; t++) {
        int tt = dir ? (Tl - 1 - t) : t;
        int pin = t & 1, pout = pin ^ 1;
        const float* hin = g_h + (size_t)(pin * 2 + dir) * 64 * 256;

        // single coalesced load of all 4 gate pre-activations
        float4 xg = __ldg((const float4*)&xw[((size_t)b * Tl + tt) * 1024 + (hu << 2)]);

        __syncthreads();
        for (int i = tid; i < 64 * 64; i += 256) {
            int bb = i >> 6, kq = (i & 63) << 2;
            *(float4*)&sh_x[bb * 260 + kq] = __ldcg((const float4*)&hin[bb * 256 + kq]);
        }
        __syncthreads();

        ull A0 = 0ull, A1 = 0ull, A2 = 0ull, A3 = 0ull;
#pragma unroll 8
        for (int kk = 0; kk < 256; kk += 4) {
            UP h, w0, w1, w2, w3;
            h.f  = *(const float4*)&sh_x[b * 260 + kk];
            w0.f = *(const float4*)&sh_w[(0 * 4 + u) * 264 + kk];
            w1.f = *(const float4*)&sh_w[(1 * 4 + u) * 264 + kk];
            w2.f = *(const float4*)&sh_w[(2 * 4 + u) * 264 + kk];
            w3.f = *(const float4*)&sh_w[(3 * 4 + u) * 264 + kk];
            fma2(A0, h.u[0], w0.u[0]); fma2(A1, h.u[0], w1.u[0]);
            fma2(A2, h.u[0], w2.u[0]); fma2(A3, h.u[0], w3.u[0]);
            fma2(A0, h.u[1], w0.u[1]); fma2(A1, h.u[1], w1.u[1]);
            fma2(A2, h.u[1], w2.u[1]); fma2(A3, h.u[1], w3.u[1]);
        }
        U2 r0, r1, r2, r3;
        r0.u = A0; r1.u = A1; r2.u = A2; r3.u = A3;
        float zi = r0.f.x + r0.f.y + xg.x;
        float zf = r1.f.x + r1.f.y + xg.y;
        float zg = r2.f.x + r2.f.y + xg.z;
        float zo = r3.f.x + r3.f.y + xg.w;
        float si = 1.f / (1.f + expf(-zi));
        float sf = 1.f / (1.f + expf(-zf));
        float so = 1.f / (1.f + expf(-zo));
        float cn = sf * creg + si * tanhf(zg);
        float hn = so * tanhf(cn);
        creg = cn;
        __stcg(&g_h[(size_t)(pout * 2 + dir) * 64 * 256 + b * 256 + hu], hn);
        out[((size_t)b * Tl + tt) * 512 + dir * 256 + hu] = hn;
        gbar(ctr, epoch, nb);
    }
    g_c[(size_t)(dir * 64 + b) * 256 + hu] = creg;
}

// ---------------- persistent decoder (LSTM step + attention fused) ---------
#define DEC_SMEM ((16 * 1032 + 64 * 132 + 512 + 128 + 256 + 512 + 64 + 256) * 4)
__global__ __launch_bounds__(256) void dec_scan(
    const float* __restrict__ sWih, const float* __restrict__ sWhh,
    const float* __restrict__ sb, const int* __restrict__ gt,
    const float* __restrict__ phi_b,
    const float* __restrict__ fcW, const float* __restrict__ fcb,
    float* __restrict__ out_lps)
{
    extern __shared__ float smem[];
    float* sh_w  = smem;
    float* sh_x  = sh_w + 16 * 1032;
    float* sh_h  = sh_x + 64 * 132;
    float* sh_q  = sh_h + 512;
    float* sh_e  = sh_q + 128;
    float* sh_c2 = sh_e + 256;
    float* sh_l  = sh_c2 + 512;
    float* sr    = sh_l + 64;

    int tid = threadIdx.x;
    int lane = tid & 31, wrp = tid >> 5;
    int u = wrp & 3, bh = wrp >> 2;
    int b = bh * 32 + lane;
    int hu0 = blockIdx.x << 2;
    int hu = hu0 + u;
    unsigned epoch = 0;
    const unsigned nb = gridDim.x;
    unsigned* ctr = &g_barD;

    for (int i = tid; i < 16 * 256; i += 256) {
        int r = i >> 8, kq = (i & 255) << 2;
        int grow = (r >> 2) * SHID + hu0 + (r & 3);
        float4 v;
        if (kq < 512) v = *(const float4*)&sWih[(size_t)grow * 560 + 48 + kq];
        else          v = *(const float4*)&sWhh[(size_t)grow * 512 + (kq - 512)];
        *(float4*)&sh_w[r * 1032 + kq] = v;
    }

    float creg = 0.f;
    __stcg(&g_dh[(size_t)b * 512 + hu], 0.f);
    __stcg(&g_ctx[(size_t)b * 512 + hu], __ldg(&g_feats[(size_t)b * 256 * 512 + hu]));
    gbar(ctr, epoch, nb);

    float bi0 = sb[0 * SHID + hu], bi1 = sb[1 * SHID + hu];
    float bi2 = sb[2 * SHID + hu], bi3 = sb[3 * SHID + hu];

    for (int t = 0; t < TDEC; t++) {
        int pin = t & 1, pout = pin ^ 1;
        int tok = (t == 0) ? 0 : gt[b * TDEC + (t - 1)];
        U2 A0, A1, A2, A3;
        A0.f = make_float2(sWih[(size_t)(0 * SHID + hu) * 560 + tok] + bi0, 0.f);
        A1.f = make_float2(sWih[(size_t)(1 * SHID + hu) * 560 + tok] + bi1, 0.f);
        A2.f = make_float2(sWih[(size_t)(2 * SHID + hu) * 560 + tok] + bi2, 0.f);
        A3.f = make_float2(sWih[(size_t)(3 * SHID + hu) * 560 + tok] + bi3, 0.f);

        const float* hin = g_dh + (size_t)pin * 64 * 512;
        for (int c = 0; c < 8; c++) {
            __syncthreads();
            const float* src = (c < 4) ? (g_ctx + (c << 7)) : (hin + ((c - 4) << 7));
            for (int i = tid; i < 64 * 32; i += 256) {
                int bb = i >> 5, kq = (i & 31) << 2;
                *(float4*)&sh_x[bb * 132 + kq] = __ldcg((const float4*)&src[(size_t)bb * 512 + kq]);
            }
            __syncthreads();
            const float* wp = sh_w + c * 128;
#pragma unroll 8
            for (int kk = 0; kk < 128; kk += 4) {
                UP h, w0, w1, w2, w3;
                h.f  = *(const float4*)&sh_x[b * 132 + kk];
                w0.f = *(const float4*)&wp[(0 * 4 + u) * 1032 + kk];
                w1.f = *(const float4*)&wp[(1 * 4 + u) * 1032 + kk];
                w2.f = *(const float4*)&wp[(2 * 4 + u) * 1032 + kk];
                w3.f = *(const float4*)&wp[(3 * 4 + u) * 1032 + kk];
                fma2(A0.u, h.u[0], w0.u[0]); fma2(A1.u, h.u[0], w1.u[0]);
                fma2(A2.u, h.u[0], w2.u[0]); fma2(A3.u, h.u[0], w3.u[0]);
                fma2(A0.u, h.u[1], w0.u[1]); fma2(A1.u, h.u[1], w1.u[1]);
                fma2(A2.u, h.u[1], w2.u[1]); fma2(A3.u, h.u[1], w3.u[1]);
            }
        }
        float acc0 = A0.f.x + A0.f.y;
        float acc1 = A1.f.x + A1.f.y;
        float acc2 = A2.f.x + A2.f.y;
        float acc3 = A3.f.x + A3.f.y;
        float si = 1.f / (1.f + expf(-acc0));
        float sf = 1.f / (1.f + expf(-acc1));
        float so = 1.f / (1.f + expf(-acc3));
        float cn = sf * creg + si * tanhf(acc2);
        float hn = so * tanhf(cn);
        creg = cn;
        __stcg(&g_dh[(size_t)pout * 64 * 512 + b * 512 + hu], hn);
        gbar(ctr, epoch, nb);

        if (blockIdx.x < 64) {
            int bb = blockIdx.x;
            const float* h = g_dh + (size_t)pout * 64 * 512 + (size_t)bb * 512;
            for (int i = tid; i < 512; i += 256) sh_h[i] = __ldcg(&h[i]);
            __syncthreads();

            if (tid < 128) {
                float a0 = 0.f, a1 = 0.f, a2 = 0.f, a3 = 0.f;
                for (int k = 0; k < 512; k += 4) {
                    a0 += sh_h[k + 0] * g_phiWt[(k + 0) * 128 + tid];
                    a1 += sh_h[k + 1] * g_phiWt[(k + 1) * 128 + tid];
                    a2 += sh_h[k + 2] * g_phiWt[(k + 2) * 128 + tid];
                    a3 += sh_h[k + 3] * g_phiWt[(k + 3) * 128 + tid];
                }
                float q = a0 + a1 + a2 + a3 + phi_b[tid];
                sh_q[tid] = q > 0.f ? q : 0.f;
            }
            __syncthreads();

            {
                const float* cfp = g_cf + ((size_t)bb * 256 + tid) * 128;
                float a0 = 0.f, a1 = 0.f, a2 = 0.f, a3 = 0.f;
                for (int j = 0; j < 128; j += 4) {
                    a0 += sh_q[j + 0] * cfp[j + 0];
                    a1 += sh_q[j + 1] * cfp[j + 1];
                    a2 += sh_q[j + 2] * cfp[j + 2];
                    a3 += sh_q[j + 3] * cfp[j + 3];
                }
                sh_e[tid] = a0 + a1 + a2 + a3;
            }
            __syncthreads();

            float v = sh_e[tid];
            sr[tid] = v; __syncthreads();
            for (int s = 128; s > 0; s >>= 1) { if (tid < s) sr[tid] = fmaxf(sr[tid], sr[tid + s]); __syncthreads(); }
            float m = sr[0]; __syncthreads();
            float e = expf(v - m);
            sr[tid] = e; __syncthreads();
            for (int s = 128; s > 0; s >>= 1) { if (tid < s) sr[tid] += sr[tid + s]; __syncthreads(); }
            float inv = 1.f / sr[0];
            __syncthreads();
            sh_e[tid] = e * inv;
            __syncthreads();

            for (int d0 = 0; d0 < 512; d0 += 256) {
                int d = d0 + tid;
                const float* fp = g_feats + (size_t)bb * 256 * 512 + d;
                float a0 = 0.f, a1 = 0.f, a2 = 0.f, a3 = 0.f;
                for (int tt2 = 0; tt2 < 256; tt2 += 4) {
                    a0 += sh_e[tt2 + 0] * fp[(size_t)(tt2 + 0) * 512];
                    a1 += sh_e[tt2 + 1] * fp[(size_t)(tt2 + 1) * 512];
                    a2 += sh_e[tt2 + 2] * fp[(size_t)(tt2 + 2) * 512];
                    a3 += sh_e[tt2 + 3] * fp[(size_t)(tt2 + 3) * 512];
                }
                float cv = a0 + a1 + a2 + a3;
                sh_c2[d] = cv;
                __stcg(&g_ctx[(size_t)bb * 512 + d], cv);
            }
            __syncthreads();

            if (tid < 48) {
                const float* wr = fcW + (size_t)tid * 1024;
                float a0 = 0.f, a1 = 0.f;
                for (int k = 0; k < 512; k++) {
                    a0 += sh_h[k] * wr[k];
                    a1 += sh_c2[k] * wr[512 + k];
                }
                sh_l[tid] = a0 + a1 + fcb[tid];
            }
            __syncthreads();
            if (tid < 48) {
                float m2 = -1e30f;
                for (int j = 0; j < 48; j++) m2 = fmaxf(m2, sh_l[j]);
                float s2 = 0.f;
                for (int j = 0; j < 48; j++) s2 += expf(sh_l[j] - m2);
                out_lps[(size_t)bb * TDEC * NVOC + (size_t)t * NVOC + tid] = sh_l[tid] - m2 - logf(s2);
            }
        }
        gbar(ctr, epoch, nb);
    }
}

// ---------------- small helpers ----------------
__global__ void transpose_phi(const float* __restrict__ W) {
    int j = blockIdx.x;
    for (int k = threadIdx.x; k < 512; k += 256) g_phiWt[k * 128 + j] = W[j * 512 + k];
}

__global__ void fin_hc(float* __restrict__ out) {
    int b = blockIdx.x;
    for (int i = threadIdx.x; i < 1024; i += 256) {
        int q = i >> 8, r = i & 255;
        float v;
        if (q == 0)      v = g_h[(size_t)(0 * 2 + 0) * 64 * 256 + b * 256 + r];
        else if (q == 1) v = g_h[(size_t)(0 * 2 + 1) * 64 * 256 + b * 256 + r];
        else if (q == 2) v = g_c[(size_t)(0 * 64 + b) * 256 + r];
        else             v = g_c[(size_t)(1 * 64 + b) * 256 + r];
        out[(size_t)b * 1024 + i] = v;
    }
}

// ---------------- host launcher ----------------
extern "C" void kernel_launch(void* const* d_in, const int* in_sizes, int n_in,
                              void* d_out, int out_size)
{
    const float* inputs = (const float*)d_in[0];
    const int*   gt     = (const int*)d_in[1];
    const float* W[27];
    for (int i = 0; i < 27; i++) W[i] = (const float*)d_in[i + 2];

    float *xw0, *xw1, *out0, *out1, *feats, *cf;
    cudaGetSymbolAddress((void**)&xw0, g_xw0);
    cudaGetSymbolAddress((void**)&xw1, g_xw1);
    cudaGetSymbolAddress((void**)&out0, g_out0);
    cudaGetSymbolAddress((void**)&out1, g_out1);
    cudaGetSymbolAddress((void**)&feats, g_feats);
    cudaGetSymbolAddress((void**)&cf, g_cf);

    cudaFuncSetAttribute(enc_scan, cudaFuncAttributeMaxDynamicSharedMemorySize, ENC_SMEM);
    cudaFuncSetAttribute(dec_scan, cudaFuncAttributeMaxDynamicSharedMemorySize, DEC_SMEM);

    float* dout = (float*)d_out;

    // launch-index padding: indices 0..2 so that index 5 = layer-0 enc_scan
    reset_bars<<<1, 32>>>();
    nop_kernel<<<1, 32>>>();
    nop_kernel<<<1, 32>>>();

    // ---------------- encoder ----------------
    const float* A = inputs;
    float* outs[3] = {out0, out1, feats};
    int Tl = 1024, K = 160;
    unsigned ebase = 0;
    for (int l = 0; l < 3; l++) {
        int M = 64 * Tl;
        dim3 gg(1024 / 64, M / 128);
        gemm_bias<<<gg, 256>>>(A, W[l * 6 + 0], W[l * 6 + 2], xw0, M, 1024, K, 0, 1);
        gemm_bias<<<gg, 256>>>(A, W[l * 6 + 3], W[l * 6 + 5], xw1, M, 1024, K, 0, 1);
        enc_scan<<<dim3(64, 2), 256, ENC_SMEM>>>(xw0, xw1, W[l * 6 + 1], W[l * 6 + 4],
                                                 outs[l], Tl, ebase);
        ebase += 64u * (unsigned)(Tl + 1);
        A = outs[l];
        Tl >>= 1;
        K = 1024;
    }

    // comp_feat = relu(feats @ psi_W^T + psi_b)   [16384,128]
    gemm_bias<<<dim3(2, 16384 / 128), 256>>>(feats, W[23], W[24], cf, 16384, 128, 512, 1, 0);
    transpose_phi<<<128, 256>>>(W[21]);
    fin_hc<<<64, 256>>>(dout + (size_t)BATCH * TDEC * NVOC);

    // ---------------- decoder ----------------
    dec_scan<<<128, 256, DEC_SMEM>>>(W[18], W[19], W[20], gt, W[22], W[25], W[26], dout);
}

// round 7
// speedup vs baseline: 1.3203x; 1.2164x over previous
#include <cuda_runtime.h>
#include <math.h>

// ---------------- problem constants ----------------
#define BATCH 64
#define TDEC  150
#define NVOC  48
#define LHID  256
#define SHID  512
#define NMLP  128

typedef unsigned long long ull;

// ---------------- device scratch ----------------
__device__ float g_xw0[64*1024*1024];
__device__ float g_xw1[64*1024*1024];
__device__ float g_out0[64*1024*512];
__device__ float g_out1[64*512*512];
__device__ float g_feats[64*256*512];
__device__ float g_cf[64*256*128];
__device__ float g_h[2*2*64*256];          // [parity][dir][b][256]
__device__ float g_c[2*64*256];
__device__ float g_dh[2*64*512];
__device__ float g_ctx[64*512];
__device__ float g_phiWt[512*128];
__device__ unsigned g_barE[2];             // per-direction encoder barriers
__device__ unsigned g_barD;                // decoder barrier

// ---------------- software grid barrier (release/acquire + backoff) --------
__device__ __forceinline__ void gbar(unsigned* ctr, unsigned& epoch, unsigned nb)
{
    __syncthreads();
    if (threadIdx.x == 0) {
        unsigned target = epoch + nb;
        asm volatile("red.release.gpu.global.add.u32 [%0], %1;"
                     :: "l"(ctr), "r"(1u) : "memory");
        unsigned v;
        asm volatile("ld.acquire.gpu.global.u32 %0, [%1];"
                     : "=r"(v) : "l"(ctr) : "memory");
        while (v < target) {
            __nanosleep(64);
            asm volatile("ld.acquire.gpu.global.u32 %0, [%1];"
                         : "=r"(v) : "l"(ctr) : "memory");
        }
    }
    epoch += nb;
    __syncthreads();
}

// ---------------- packed fp32x2 FMA (SASS FFMA2) ----------------
__device__ __forceinline__ void fma2(ull& d, ull a, ull b)
{
    asm("fma.rn.f32x2 %0, %1, %2, %0;" : "+l"(d) : "l"(a), "l"(b));
}

union UP { float4 f; ull u[2]; };
union U2 { ull u; float2 f; };

// ---------------- barrier reset + pad launches ----------------
__global__ void reset_bars() {
    if (threadIdx.x == 0 && blockIdx.x == 0) {
        g_barE[0] = 0; g_barE[1] = 0; g_barD = 0;
    }
}
__global__ void nop_kernel() {}

// ---------------- fp32 GEMM (R2-proven tile): C = A@W^T + bias -------------
// Tile 128(M) x 64(N), BK=16, 256 threads, 8x4 per thread.
// gate_perm: output column n' maps to weight/bias row (n'&3)*256 + (n'>>2).
__global__ __launch_bounds__(256) void gemm_bias(
    const float* __restrict__ A, const float* __restrict__ W,
    const float* __restrict__ bias, float* __restrict__ C,
    int M, int N, int K, int relu, int gate_perm)
{
    __shared__ float As[16 * 132];
    __shared__ float Ws[16 * 68];
    int bm = blockIdx.y << 7, bn = blockIdx.x << 6;
    int tid = threadIdx.x;
    int ty = tid >> 4, tx = tid & 15;
    const float* Ap = A + (size_t)bm * K;

    int wr = tid >> 2, wc = (tid & 3) << 2;
    int nprime = bn + wr;
    int nrow = gate_perm ? ((nprime & 3) * 256 + (nprime >> 2)) : nprime;
    const float* WpRow = W + (size_t)nrow * K;

    float acc[8][4];
#pragma unroll
    for (int i = 0; i < 8; i++)
#pragma unroll
        for (int j = 0; j < 4; j++) acc[i][j] = 0.f;

    for (int k0 = 0; k0 < K; k0 += 16) {
#pragma unroll
        for (int j = 0; j < 2; j++) {
            int idx = tid + 256 * j;
            int r = idx >> 2, c = (idx & 3) << 2;
            float4 v = *(const float4*)&Ap[(size_t)r * K + k0 + c];
            As[(c + 0) * 132 + r] = v.x;
            As[(c + 1) * 132 + r] = v.y;
            As[(c + 2) * 132 + r] = v.z;
            As[(c + 3) * 132 + r] = v.w;
        }
        {
            float4 v = *(const float4*)&WpRow[k0 + wc];
            Ws[(wc + 0) * 68 + wr] = v.x;
            Ws[(wc + 1) * 68 + wr] = v.y;
            Ws[(wc + 2) * 68 + wr] = v.z;
            Ws[(wc + 3) * 68 + wr] = v.w;
        }
        __syncthreads();
#pragma unroll
        for (int kk = 0; kk < 16; kk++) {
            float4 a0 = *(const float4*)&As[kk * 132 + ty * 8];
            float4 a1 = *(const float4*)&As[kk * 132 + ty * 8 + 4];
            float4 w  = *(const float4*)&Ws[kk * 68 + tx * 4];
            acc[0][0] += a0.x * w.x; acc[0][1] += a0.x * w.y; acc[0][2] += a0.x * w.z; acc[0][3] += a0.x * w.w;
            acc[1][0] += a0.y * w.x; acc[1][1] += a0.y * w.y; acc[1][2] += a0.y * w.z; acc[1][3] += a0.y * w.w;
            acc[2][0] += a0.z * w.x; acc[2][1] += a0.z * w.y; acc[2][2] += a0.z * w.z; acc[2][3] += a0.z * w.w;
            acc[3][0] += a0.w * w.x; acc[3][1] += a0.w * w.y; acc[3][2] += a0.w * w.z; acc[3][3] += a0.w * w.w;
            acc[4][0] += a1.x * w.x; acc[4][1] += a1.x * w.y; acc[4][2] += a1.x * w.z; acc[4][3] += a1.x * w.w;
            acc[5][0] += a1.y * w.x; acc[5][1] += a1.y * w.y; acc[5][2] += a1.y * w.z; acc[5][3] += a1.y * w.w;
            acc[6][0] += a1.z * w.x; acc[6][1] += a1.z * w.y; acc[6][2] += a1.z * w.z; acc[6][3] += a1.z * w.w;
            acc[7][0] += a1.w * w.x; acc[7][1] += a1.w * w.y; acc[7][2] += a1.w * w.z; acc[7][3] += a1.w * w.w;
        }
        __syncthreads();
    }
    float bvx, bvy, bvz, bvw;
    if (gate_perm) {
        int n0 = bn + tx * 4;
        bvx = bias[((n0 + 0) & 3) * 256 + ((n0 + 0) >> 2)];
        bvy = bias[((n0 + 1) & 3) * 256 + ((n0 + 1) >> 2)];
        bvz = bias[((n0 + 2) & 3) * 256 + ((n0 + 2) >> 2)];
        bvw = bias[((n0 + 3) & 3) * 256 + ((n0 + 3) >> 2)];
    } else {
        float4 bv = *(const float4*)&bias[bn + tx * 4];
        bvx = bv.x; bvy = bv.y; bvz = bv.z; bvw = bv.w;
    }
#pragma unroll
    for (int i = 0; i < 8; i++) {
        int m = bm + ty * 8 + i;
        float4 o;
        o.x = acc[i][0] + bvx; o.y = acc[i][1] + bvy;
        o.z = acc[i][2] + bvz; o.w = acc[i][3] + bvw;
        if (relu) {
            o.x = fmaxf(o.x, 0.f); o.y = fmaxf(o.y, 0.f);
            o.z = fmaxf(o.z, 0.f); o.w = fmaxf(o.w, 0.f);
        }
        *(float4*)&C[(size_t)m * N + bn + tx * 4] = o;
    }
}

// ---------------- persistent encoder scan (R5-proven) ----------------
// xw is gate-interleaved: xw[(b*Tl+t)*1024 + hu*4 + gate]
#define ENC_SMEM ((16 * 264 + 64 * 260) * 4)
__global__ __launch_bounds__(256) void enc_scan(
    const float* __restrict__ xw_f, const float* __restrict__ xw_b,
    const float* __restrict__ whh_f, const float* __restrict__ whh_b,
    float* __restrict__ out, int Tl, unsigned epoch0)
{
    extern __shared__ float smem[];
    float* sh_w = smem;               // 16 x 256 (pitch 264)
    float* sh_x = smem + 16 * 264;    // 64 x 256 (pitch 260)

    int tid = threadIdx.x;
    int lane = tid & 31, wrp = tid >> 5;
    int u = wrp & 3, bh = wrp >> 2;
    int b = bh * 32 + lane;
    int dir = blockIdx.y;
    int hu0 = blockIdx.x << 2;
    int hu = hu0 + u;
    unsigned epoch = epoch0;
    const unsigned nb = gridDim.x;       // 64 blocks per direction
    unsigned* ctr = &g_barE[dir];

    const float* xw  = dir ? xw_b  : xw_f;
    const float* Whh = dir ? whh_b : whh_f;

    for (int i = tid; i < 16 * 64; i += 256) {
        int r = i >> 6, kq = (i & 63) << 2;
        int grow = ((r >> 2) << 8) + hu0 + (r & 3);
        *(float4*)&sh_w[r * 264 + kq] = *(const float4*)&Whh[(size_t)grow * 256 + kq];
    }

    float creg = 0.f;
    __stcg(&g_h[(size_t)(0 * 2 + dir) * 64 * 256 + b * 256 + hu], 0.f);
    gbar(ctr, epoch, nb);

    for (int t = 0; t < Tl; t++) {
        int tt = dir ? (Tl - 1 - t) : t;
        int pin = t & 1, pout = pin ^ 1;
        const float* hin = g_h + (size_t)(pin * 2 + dir) * 64 * 256;

        float4 xg = __ldg((const float4*)&xw[((size_t)b * Tl + tt) * 1024 + (hu << 2)]);

        __syncthreads();
        for (int i = tid; i < 64 * 64; i += 256) {
            int bb = i >> 6, kq = (i & 63) << 2;
            *(float4*)&sh_x[bb * 260 + kq] = __ldcg((const float4*)&hin[bb * 256 + kq]);
        }
        __syncthreads();

        ull A0 = 0ull, A1 = 0ull, A2 = 0ull, A3 = 0ull;
#pragma unroll 8
        for (int kk = 0; kk < 256; kk += 4) {
            UP h, w0, w1, w2, w3;
            h.f  = *(const float4*)&sh_x[b * 260 + kk];
            w0.f = *(const float4*)&sh_w[(0 * 4 + u) * 264 + kk];
            w1.f = *(const float4*)&sh_w[(1 * 4 + u) * 264 + kk];
            w2.f = *(const float4*)&sh_w[(2 * 4 + u) * 264 + kk];
            w3.f = *(const float4*)&sh_w[(3 * 4 + u) * 264 + kk];
            fma2(A0, h.u[0], w0.u[0]); fma2(A1, h.u[0], w1.u[0]);
            fma2(A2, h.u[0], w2.u[0]); fma2(A3, h.u[0], w3.u[0]);
            fma2(A0, h.u[1], w0.u[1]); fma2(A1, h.u[1], w1.u[1]);
            fma2(A2, h.u[1], w2.u[1]); fma2(A3, h.u[1], w3.u[1]);
        }
        U2 r0, r1, r2, r3;
        r0.u = A0; r1.u = A1; r2.u = A2; r3.u = A3;
        float zi = r0.f.x + r0.f.y + xg.x;
        float zf = r1.f.x + r1.f.y + xg.y;
        float zg = r2.f.x + r2.f.y + xg.z;
        float zo = r3.f.x + r3.f.y + xg.w;
        float si = 1.f / (1.f + expf(-zi));
        float sf = 1.f / (1.f + expf(-zf));
        float so = 1.f / (1.f + expf(-zo));
        float cn = sf * creg + si * tanhf(zg);
        float hn = so * tanhf(cn);
        creg = cn;
        __stcg(&g_h[(size_t)(pout * 2 + dir) * 64 * 256 + b * 256 + hu], hn);
        out[((size_t)b * Tl + tt) * 512 + dir * 256 + hu] = hn;
        gbar(ctr, epoch, nb);
    }
    g_c[(size_t)(dir * 64 + b) * 256 + hu] = creg;
}

// ---------------- persistent decoder (LSTM step + attention fused) ---------
#define DEC_SMEM ((16 * 1032 + 64 * 132 + 512 + 128 + 256 + 512 + 64 + 256) * 4)
__global__ __launch_bounds__(256) void dec_scan(
    const float* __restrict__ sWih, const float* __restrict__ sWhh,
    const float* __restrict__ sb, const int* __restrict__ gt,
    const float* __restrict__ phi_b,
    const float* __restrict__ fcW, const float* __restrict__ fcb,
    float* __restrict__ out_lps)
{
    extern __shared__ float smem[];
    float* sh_w  = smem;
    float* sh_x  = sh_w + 16 * 1032;
    float* sh_h  = sh_x + 64 * 132;
    float* sh_q  = sh_h + 512;
    float* sh_e  = sh_q + 128;
    float* sh_c2 = sh_e + 256;
    float* sh_l  = sh_c2 + 512;
    float* sr    = sh_l + 64;          // 256 scratch (softmax reduce / partials)

    int tid = threadIdx.x;
    int lane = tid & 31, wrp = tid >> 5;
    int u = wrp & 3, bh = wrp >> 2;
    int b = bh * 32 + lane;
    int hu0 = blockIdx.x << 2;
    int hu = hu0 + u;
    unsigned epoch = 0;
    const unsigned nb = gridDim.x;
    unsigned* ctr = &g_barD;

    for (int i = tid; i < 16 * 256; i += 256) {
        int r = i >> 8, kq = (i & 255) << 2;
        int grow = (r >> 2) * SHID + hu0 + (r & 3);
        float4 v;
        if (kq < 512) v = *(const float4*)&sWih[(size_t)grow * 560 + 48 + kq];
        else          v = *(const float4*)&sWhh[(size_t)grow * 512 + (kq - 512)];
        *(float4*)&sh_w[r * 1032 + kq] = v;
    }

    float creg = 0.f;
    __stcg(&g_dh[(size_t)b * 512 + hu], 0.f);
    __stcg(&g_ctx[(size_t)b * 512 + hu], __ldg(&g_feats[(size_t)b * 256 * 512 + hu]));
    gbar(ctr, epoch, nb);

    float bi0 = sb[0 * SHID + hu], bi1 = sb[1 * SHID + hu];
    float bi2 = sb[2 * SHID + hu], bi3 = sb[3 * SHID + hu];

    for (int t = 0; t < TDEC; t++) {
        int pin = t & 1, pout = pin ^ 1;
        int tok = (t == 0) ? 0 : gt[b * TDEC + (t - 1)];
        U2 A0, A1, A2, A3;
        A0.f = make_float2(sWih[(size_t)(0 * SHID + hu) * 560 + tok] + bi0, 0.f);
        A1.f = make_float2(sWih[(size_t)(1 * SHID + hu) * 560 + tok] + bi1, 0.f);
        A2.f = make_float2(sWih[(size_t)(2 * SHID + hu) * 560 + tok] + bi2, 0.f);
        A3.f = make_float2(sWih[(size_t)(3 * SHID + hu) * 560 + tok] + bi3, 0.f);

        const float* hin = g_dh + (size_t)pin * 64 * 512;
        for (int c = 0; c < 8; c++) {
            __syncthreads();
            const float* src = (c < 4) ? (g_ctx + (c << 7)) : (hin + ((c - 4) << 7));
            for (int i = tid; i < 64 * 32; i += 256) {
                int bb = i >> 5, kq = (i & 31) << 2;
                *(float4*)&sh_x[bb * 132 + kq] = __ldcg((const float4*)&src[(size_t)bb * 512 + kq]);
            }
            __syncthreads();
            const float* wp = sh_w + c * 128;
#pragma unroll 8
            for (int kk = 0; kk < 128; kk += 4) {
                UP h, w0, w1, w2, w3;
                h.f  = *(const float4*)&sh_x[b * 132 + kk];
                w0.f = *(const float4*)&wp[(0 * 4 + u) * 1032 + kk];
                w1.f = *(const float4*)&wp[(1 * 4 + u) * 1032 + kk];
                w2.f = *(const float4*)&wp[(2 * 4 + u) * 1032 + kk];
                w3.f = *(const float4*)&wp[(3 * 4 + u) * 1032 + kk];
                fma2(A0.u, h.u[0], w0.u[0]); fma2(A1.u, h.u[0], w1.u[0]);
                fma2(A2.u, h.u[0], w2.u[0]); fma2(A3.u, h.u[0], w3.u[0]);
                fma2(A0.u, h.u[1], w0.u[1]); fma2(A1.u, h.u[1], w1.u[1]);
                fma2(A2.u, h.u[1], w2.u[1]); fma2(A3.u, h.u[1], w3.u[1]);
            }
        }
        float acc0 = A0.f.x + A0.f.y;
        float acc1 = A1.f.x + A1.f.y;
        float acc2 = A2.f.x + A2.f.y;
        float acc3 = A3.f.x + A3.f.y;
        float si = 1.f / (1.f + expf(-acc0));
        float sf = 1.f / (1.f + expf(-acc1));
        float so = 1.f / (1.f + expf(-acc3));
        float cn = sf * creg + si * tanhf(acc2);
        float hn = so * tanhf(cn);
        creg = cn;
        __stcg(&g_dh[(size_t)pout * 64 * 512 + b * 512 + hu], hn);
        gbar(ctr, epoch, nb);

        if (blockIdx.x < 64) {
            int bb = blockIdx.x;
            const float* h = g_dh + (size_t)pout * 64 * 512 + (size_t)bb * 512;
            for (int i = tid; i < 512; i += 256) sh_h[i] = __ldcg(&h[i]);
            __syncthreads();

            // phi GEMV: 256 threads, j = tid>>1 (0..127), half = tid&1
            {
                int j = tid >> 1, hf = tid & 1;
                const float* pw = g_phiWt + (size_t)hf * 256 * 128;
                const float* hh = sh_h + hf * 256;
                float a0 = 0.f, a1 = 0.f, a2 = 0.f, a3 = 0.f;
                for (int k = 0; k < 256; k += 4) {
                    a0 += hh[k + 0] * pw[(k + 0) * 128 + j];
                    a1 += hh[k + 1] * pw[(k + 1) * 128 + j];
                    a2 += hh[k + 2] * pw[(k + 2) * 128 + j];
                    a3 += hh[k + 3] * pw[(k + 3) * 128 + j];
                }
                sr[tid] = a0 + a1 + a2 + a3;
            }
            __syncthreads();
            if (tid < 128) {
                float q = sr[2 * tid] + sr[2 * tid + 1] + phi_b[tid];
                sh_q[tid] = q > 0.f ? q : 0.f;
            }
            __syncthreads();

            // scores e[t'] = q . comp_feat[b,t',:]
            {
                const float* cfp = g_cf + ((size_t)bb * 256 + tid) * 128;
                float a0 = 0.f, a1 = 0.f, a2 = 0.f, a3 = 0.f;
                for (int j = 0; j < 128; j += 4) {
                    a0 += sh_q[j + 0] * cfp[j + 0];
                    a1 += sh_q[j + 1] * cfp[j + 1];
                    a2 += sh_q[j + 2] * cfp[j + 2];
                    a3 += sh_q[j + 3] * cfp[j + 3];
                }
                sh_e[tid] = a0 + a1 + a2 + a3;
            }
            __syncthreads();

            float v = sh_e[tid];
            sr[tid] = v; __syncthreads();
            for (int s = 128; s > 0; s >>= 1) { if (tid < s) sr[tid] = fmaxf(sr[tid], sr[tid + s]); __syncthreads(); }
            float m = sr[0]; __syncthreads();
            float e = expf(v - m);
            sr[tid] = e; __syncthreads();
            for (int s = 128; s > 0; s >>= 1) { if (tid < s) sr[tid] += sr[tid + s]; __syncthreads(); }
            float inv = 1.f / sr[0];
            __syncthreads();
            sh_e[tid] = e * inv;
            __syncthreads();

            for (int d0 = 0; d0 < 512; d0 += 256) {
                int d = d0 + tid;
                const float* fp = g_feats + (size_t)bb * 256 * 512 + d;
                float a0 = 0.f, a1 = 0.f, a2 = 0.f, a3 = 0.f;
                for (int tt2 = 0; tt2 < 256; tt2 += 4) {
                    a0 += sh_e[tt2 + 0] * fp[(size_t)(tt2 + 0) * 512];
                    a1 += sh_e[tt2 + 1] * fp[(size_t)(tt2 + 1) * 512];
                    a2 += sh_e[tt2 + 2] * fp[(size_t)(tt2 + 2) * 512];
                    a3 += sh_e[tt2 + 3] * fp[(size_t)(tt2 + 3) * 512];
                }
                float cv = a0 + a1 + a2 + a3;
                sh_c2[d] = cv;
                __stcg(&g_ctx[(size_t)bb * 512 + d], cv);
            }
            __syncthreads();

            // fc logits: 192 threads, v = tid>>2 (0..47), part = tid&3
            if (tid < 192) {
                int v2 = tid >> 2, part = tid & 3;
                const float* wr = fcW + (size_t)v2 * 1024 + part * 256;
                const float* src = (part < 2) ? (sh_h + part * 256) : (sh_c2 + (part - 2) * 256);
                float a0 = 0.f, a1 = 0.f, a2 = 0.f, a3 = 0.f;
                for (int k = 0; k < 256; k += 4) {
                    a0 += src[k + 0] * wr[k + 0];
                    a1 += src[k + 1] * wr[k + 1];
                    a2 += src[k + 2] * wr[k + 2];
                    a3 += src[k + 3] * wr[k + 3];
                }
                sr[tid] = a0 + a1 + a2 + a3;
            }
            __syncthreads();
            if (tid < 48) {
                sh_l[tid] = sr[tid * 4] + sr[tid * 4 + 1] + sr[tid * 4 + 2] + sr[tid * 4 + 3] + fcb[tid];
            }
            __syncthreads();
            if (tid < 48) {
                float m2 = -1e30f;
                for (int j = 0; j < 48; j++) m2 = fmaxf(m2, sh_l[j]);
                float s2 = 0.f;
                for (int j = 0; j < 48; j++) s2 += expf(sh_l[j] - m2);
                out_lps[(size_t)bb * TDEC * NVOC + (size_t)t * NVOC + tid] = sh_l[tid] - m2 - logf(s2);
            }
        }
        gbar(ctr, epoch, nb);
    }
}

// ---------------- small helpers ----------------
__global__ void transpose_phi(const float* __restrict__ W) {
    int j = blockIdx.x;
    for (int k = threadIdx.x; k < 512; k += 256) g_phiWt[k * 128 + j] = W[j * 512 + k];
}

__global__ void fin_hc(float* __restrict__ out) {
    int b = blockIdx.x;
    for (int i = threadIdx.x; i < 1024; i += 256) {
        int q = i >> 8, r = i & 255;
        float v;
        if (q == 0)      v = g_h[(size_t)(0 * 2 + 0) * 64 * 256 + b * 256 + r];
        else if (q == 1) v = g_h[(size_t)(0 * 2 + 1) * 64 * 256 + b * 256 + r];
        else if (q == 2) v = g_c[(size_t)(0 * 64 + b) * 256 + r];
        else             v = g_c[(size_t)(1 * 64 + b) * 256 + r];
        out[(size_t)b * 1024 + i] = v;
    }
}

// ---------------- host launcher ----------------
extern "C" void kernel_launch(void* const* d_in, const int* in_sizes, int n_in,
                              void* d_out, int out_size)
{
    const float* inputs = (const float*)d_in[0];
    const int*   gt     = (const int*)d_in[1];
    const float* W[27];
    for (int i = 0; i < 27; i++) W[i] = (const float*)d_in[i + 2];

    float *xw0, *xw1, *out0, *out1, *feats, *cf;
    cudaGetSymbolAddress((void**)&xw0, g_xw0);
    cudaGetSymbolAddress((void**)&xw1, g_xw1);
    cudaGetSymbolAddress((void**)&out0, g_out0);
    cudaGetSymbolAddress((void**)&out1, g_out1);
    cudaGetSymbolAddress((void**)&feats, g_feats);
    cudaGetSymbolAddress((void**)&cf, g_cf);

    cudaFuncSetAttribute(enc_scan, cudaFuncAttributeMaxDynamicSharedMemorySize, ENC_SMEM);
    cudaFuncSetAttribute(dec_scan, cudaFuncAttributeMaxDynamicSharedMemorySize, DEC_SMEM);

    float* dout = (float*)d_out;

    reset_bars<<<1, 32>>>();
    nop_kernel<<<1, 32>>>();
    nop_kernel<<<1, 32>>>();

    // ---------------- encoder ----------------
    const float* A = inputs;
    float* outs[3] = {out0, out1, feats};
    int Tl = 1024, K = 160;
    unsigned ebase = 0;
    for (int l = 0; l < 3; l++) {
        int M = 64 * Tl;
        dim3 gg(1024 / 64, M / 128);
        gemm_bias<<<gg, 256>>>(A, W[l * 6 + 0], W[l * 6 + 2], xw0, M, 1024, K, 0, 1);
        gemm_bias<<<gg, 256>>>(A, W[l * 6 + 3], W[l * 6 + 5], xw1, M, 1024, K, 0, 1);
        enc_scan<<<dim3(64, 2), 256, ENC_SMEM>>>(xw0, xw1, W[l * 6 + 1], W[l * 6 + 4],
                                                 outs[l], Tl, ebase);
        ebase += 64u * (unsigned)(Tl + 1);
        A = outs[l];
        Tl >>= 1;
        K = 1024;
    }

    // comp_feat = relu(feats @ psi_W^T + psi_b)   [16384,128]
    gemm_bias<<<dim3(2, 16384 / 128), 256>>>(feats, W[23], W[24], cf, 16384, 128, 512, 1, 0);
    transpose_phi<<<128, 256>>>(W[21]);
    fin_hc<<<64, 256>>>(dout + (size_t)BATCH * TDEC * NVOC);

    // ---------------- decoder ----------------
    dec_scan<<<128, 256, DEC_SMEM>>>(W[18], W[19], W[20], gt, W[22], W[25], W[26], dout);
}

// round 8
// speedup vs baseline: 1.4235x; 1.0781x over previous
#include <cuda_runtime.h>
#include <math.h>

// ---------------- problem constants ----------------
#define BATCH 64
#define TDEC  150
#define NVOC  48
#define LHID  256
#define SHID  512
#define NMLP  128

typedef unsigned long long ull;

// ---------------- device scratch ----------------
__device__ float g_xw0[64*1024*1024];
__device__ float g_xw1[64*1024*1024];
__device__ float g_out0[64*1024*512];
__device__ float g_out1[64*512*512];
__device__ float g_feats[64*256*512];
__device__ float g_cf[64*256*128];
__device__ float g_h[2*2*64*256];          // [parity][dir][b][256]
__device__ float g_c[2*64*256];
__device__ float g_dh[2*64*512];
__device__ float g_ctx[64*512];
__device__ float g_phiWt[512*128];
__device__ unsigned g_barE[2];             // per-direction encoder barriers
__device__ unsigned g_barD;                // decoder barrier

// ---------------- split-phase grid barrier (R7-proven primitives) ----------
__device__ __forceinline__ void gbar_arrive(unsigned* ctr)
{
    __syncthreads();
    if (threadIdx.x == 0) {
        asm volatile("red.release.gpu.global.add.u32 [%0], %1;"
                     :: "l"(ctr), "r"(1u) : "memory");
    }
}
__device__ __forceinline__ void gbar_wait(unsigned* ctr, unsigned& epoch, unsigned nb)
{
    if (threadIdx.x == 0) {
        unsigned target = epoch + nb;
        unsigned v;
        asm volatile("ld.acquire.gpu.global.u32 %0, [%1];"
                     : "=r"(v) : "l"(ctr) : "memory");
        while (v < target) {
            __nanosleep(64);
            asm volatile("ld.acquire.gpu.global.u32 %0, [%1];"
                         : "=r"(v) : "l"(ctr) : "memory");
        }
    }
    epoch += nb;
    __syncthreads();
}
__device__ __forceinline__ void gbar(unsigned* ctr, unsigned& epoch, unsigned nb)
{
    gbar_arrive(ctr);
    gbar_wait(ctr, epoch, nb);
}

// ---------------- packed fp32x2 FMA (SASS FFMA2) ----------------
__device__ __forceinline__ void fma2(ull& d, ull a, ull b)
{
    asm("fma.rn.f32x2 %0, %1, %2, %0;" : "+l"(d) : "l"(a), "l"(b));
}

union UP { float4 f; ull u[2]; };
union U2 { ull u; float2 f; };

// ---------------- barrier reset + pad launches ----------------
__global__ void reset_bars() {
    if (threadIdx.x == 0 && blockIdx.x == 0) {
        g_barE[0] = 0; g_barE[1] = 0; g_barD = 0;
    }
}
__global__ void nop_kernel() {}

// ---------------- fp32 GEMM (R2-proven tile): C = A@W^T + bias -------------
// Tile 128(M) x 64(N), BK=16, 256 threads, 8x4 per thread.
// gate_perm: output column n' maps to weight/bias row (n'&3)*256 + (n'>>2).
__global__ __launch_bounds__(256) void gemm_bias(
    const float* __restrict__ A, const float* __restrict__ W,
    const float* __restrict__ bias, float* __restrict__ C,
    int M, int N, int K, int relu, int gate_perm)
{
    __shared__ float As[16 * 132];
    __shared__ float Ws[16 * 68];
    int bm = blockIdx.y << 7, bn = blockIdx.x << 6;
    int tid = threadIdx.x;
    int ty = tid >> 4, tx = tid & 15;
    const float* Ap = A + (size_t)bm * K;

    int wr = tid >> 2, wc = (tid & 3) << 2;
    int nprime = bn + wr;
    int nrow = gate_perm ? ((nprime & 3) * 256 + (nprime >> 2)) : nprime;
    const float* WpRow = W + (size_t)nrow * K;

    float acc[8][4];
#pragma unroll
    for (int i = 0; i < 8; i++)
#pragma unroll
        for (int j = 0; j < 4; j++) acc[i][j] = 0.f;

    for (int k0 = 0; k0 < K; k0 += 16) {
#pragma unroll
        for (int j = 0; j < 2; j++) {
            int idx = tid + 256 * j;
            int r = idx >> 2, c = (idx & 3) << 2;
            float4 v = *(const float4*)&Ap[(size_t)r * K + k0 + c];
            As[(c + 0) * 132 + r] = v.x;
            As[(c + 1) * 132 + r] = v.y;
            As[(c + 2) * 132 + r] = v.z;
            As[(c + 3) * 132 + r] = v.w;
        }
        {
            float4 v = *(const float4*)&WpRow[k0 + wc];
            Ws[(wc + 0) * 68 + wr] = v.x;
            Ws[(wc + 1) * 68 + wr] = v.y;
            Ws[(wc + 2) * 68 + wr] = v.z;
            Ws[(wc + 3) * 68 + wr] = v.w;
        }
        __syncthreads();
#pragma unroll
        for (int kk = 0; kk < 16; kk++) {
            float4 a0 = *(const float4*)&As[kk * 132 + ty * 8];
            float4 a1 = *(const float4*)&As[kk * 132 + ty * 8 + 4];
            float4 w  = *(const float4*)&Ws[kk * 68 + tx * 4];
            acc[0][0] += a0.x * w.x; acc[0][1] += a0.x * w.y; acc[0][2] += a0.x * w.z; acc[0][3] += a0.x * w.w;
            acc[1][0] += a0.y * w.x; acc[1][1] += a0.y * w.y; acc[1][2] += a0.y * w.z; acc[1][3] += a0.y * w.w;
            acc[2][0] += a0.z * w.x; acc[2][1] += a0.z * w.y; acc[2][2] += a0.z * w.z; acc[2][3] += a0.z * w.w;
            acc[3][0] += a0.w * w.x; acc[3][1] += a0.w * w.y; acc[3][2] += a0.w * w.z; acc[3][3] += a0.w * w.w;
            acc[4][0] += a1.x * w.x; acc[4][1] += a1.x * w.y; acc[4][2] += a1.x * w.z; acc[4][3] += a1.x * w.w;
            acc[5][0] += a1.y * w.x; acc[5][1] += a1.y * w.y; acc[5][2] += a1.y * w.z; acc[5][3] += a1.y * w.w;
            acc[6][0] += a1.z * w.x; acc[6][1] += a1.z * w.y; acc[6][2] += a1.z * w.z; acc[6][3] += a1.z * w.w;
            acc[7][0] += a1.w * w.x; acc[7][1] += a1.w * w.y; acc[7][2] += a1.w * w.z; acc[7][3] += a1.w * w.w;
        }
        __syncthreads();
    }
    float bvx, bvy, bvz, bvw;
    if (gate_perm) {
        int n0 = bn + tx * 4;
        bvx = bias[((n0 + 0) & 3) * 256 + ((n0 + 0) >> 2)];
        bvy = bias[((n0 + 1) & 3) * 256 + ((n0 + 1) >> 2)];
        bvz = bias[((n0 + 2) & 3) * 256 + ((n0 + 2) >> 2)];
        bvw = bias[((n0 + 3) & 3) * 256 + ((n0 + 3) >> 2)];
    } else {
        float4 bv = *(const float4*)&bias[bn + tx * 4];
        bvx = bv.x; bvy = bv.y; bvz = bv.z; bvw = bv.w;
    }
#pragma unroll
    for (int i = 0; i < 8; i++) {
        int m = bm + ty * 8 + i;
        float4 o;
        o.x = acc[i][0] + bvx; o.y = acc[i][1] + bvy;
        o.z = acc[i][2] + bvz; o.w = acc[i][3] + bvw;
        if (relu) {
            o.x = fmaxf(o.x, 0.f); o.y = fmaxf(o.y, 0.f);
            o.z = fmaxf(o.z, 0.f); o.w = fmaxf(o.w, 0.f);
        }
        *(float4*)&C[(size_t)m * N + bn + tx * 4] = o;
    }
}

// ---------------- persistent encoder scan: 512 threads, k-split ------------
// warp map: kh = wrp>>3, u = (wrp>>1)&3, bh = wrp&1.
// xw is gate-interleaved: xw[(b*Tl+t)*1024 + hu*4 + gate]
#define ENC_SMEM ((16 * 264 + 64 * 260 + 256 * 4) * 4)
__global__ __launch_bounds__(512) void enc_scan(
    const float* __restrict__ xw_f, const float* __restrict__ xw_b,
    const float* __restrict__ whh_f, const float* __restrict__ whh_b,
    float* __restrict__ out, int Tl, unsigned epoch0)
{
    extern __shared__ float smem[];
    float* sh_w = smem;               // 16 x 256 (pitch 264)
    float* sh_x = smem + 16 * 264;    // 64 x 256 (pitch 260)
    float* sh_p = sh_x + 64 * 260;    // 256 x 4 partials (kh=1 -> kh=0)

    int tid = threadIdx.x;
    int lane = tid & 31, wrp = tid >> 5;
    int kh = wrp >> 3;
    int u = (wrp >> 1) & 3;
    int bh = wrp & 1;
    int b = bh * 32 + lane;
    int dir = blockIdx.y;
    int hu0 = blockIdx.x << 2;
    int hu = hu0 + u;
    unsigned epoch = epoch0;
    const unsigned nb = gridDim.x;       // 64 blocks per direction
    unsigned* ctr = &g_barE[dir];

    const float* xw  = dir ? xw_b  : xw_f;
    const float* Whh = dir ? whh_b : whh_f;

    // resident weights: rows r = gate*4 + unit
    for (int i = tid; i < 16 * 64; i += 512) {
        int r = i >> 6, kq = (i & 63) << 2;
        int grow = ((r >> 2) << 8) + hu0 + (r & 3);
        *(float4*)&sh_w[r * 264 + kq] = *(const float4*)&Whh[(size_t)grow * 256 + kq];
    }

    float creg = 0.f;
    if (kh == 0)
        __stcg(&g_h[(size_t)(0 * 2 + dir) * 64 * 256 + b * 256 + hu], 0.f);
    gbar(ctr, epoch, nb);

    const float* wr0 = &sh_w[(0 * 4 + u) * 264 + kh * 128];
    const float* wr1 = &sh_w[(1 * 4 + u) * 264 + kh * 128];
    const float* wr2 = &sh_w[(2 * 4 + u) * 264 + kh * 128];
    const float* wr3 = &sh_w[(3 * 4 + u) * 264 + kh * 128];
    const float* hp  = &sh_x[b * 260 + kh * 128];
    float* pp = &sh_p[(u * 64 + b) * 4];

    // first-step gate prefetch
    float4 xg = make_float4(0.f, 0.f, 0.f, 0.f);
    if (kh == 0) {
        int tt0 = dir ? (Tl - 1) : 0;
        xg = __ldg((const float4*)&xw[((size_t)b * Tl + tt0) * 1024 + (hu << 2)]);
    }

    for (int t = 0; t < Tl; t++) {
        int tt = dir ? (Tl - 1 - t) : t;
        int pin = t & 1, pout = pin ^ 1;
        const float* hin = g_h + (size_t)(pin * 2 + dir) * 64 * 256;

        // broadcast fill of h (8 float4 per thread)
        for (int i = tid; i < 4096; i += 512) {
            int bb = i >> 6, kq = (i & 63) << 2;
            *(float4*)&sh_x[bb * 260 + kq] = __ldcg((const float4*)&hin[bb * 256 + kq]);
        }
        __syncthreads();

        ull A0 = 0ull, A1 = 0ull, A2 = 0ull, A3 = 0ull;
#pragma unroll 8
        for (int kk = 0; kk < 128; kk += 4) {
            UP h, w0, w1, w2, w3;
            h.f  = *(const float4*)&hp[kk];
            w0.f = *(const float4*)&wr0[kk];
            w1.f = *(const float4*)&wr1[kk];
            w2.f = *(const float4*)&wr2[kk];
            w3.f = *(const float4*)&wr3[kk];
            fma2(A0, h.u[0], w0.u[0]); fma2(A1, h.u[0], w1.u[0]);
            fma2(A2, h.u[0], w2.u[0]); fma2(A3, h.u[0], w3.u[0]);
            fma2(A0, h.u[1], w0.u[1]); fma2(A1, h.u[1], w1.u[1]);
            fma2(A2, h.u[1], w2.u[1]); fma2(A3, h.u[1], w3.u[1]);
        }
        U2 r0, r1, r2, r3;
        r0.u = A0; r1.u = A1; r2.u = A2; r3.u = A3;
        if (kh == 1) {
            *(float4*)pp = make_float4(r0.f.x + r0.f.y, r1.f.x + r1.f.y,
                                       r2.f.x + r2.f.y, r3.f.x + r3.f.y);
        }
        __syncthreads();

        float hn = 0.f;
        if (kh == 0) {
            float4 p = *(const float4*)pp;
            float zi = r0.f.x + r0.f.y + p.x + xg.x;
            float zf = r1.f.x + r1.f.y + p.y + xg.y;
            float zg = r2.f.x + r2.f.y + p.z + xg.z;
            float zo = r3.f.x + r3.f.y + p.w + xg.w;
            float si = 1.f / (1.f + expf(-zi));
            float sf = 1.f / (1.f + expf(-zf));
            float so = 1.f / (1.f + expf(-zo));
            float cn = sf * creg + si * tanhf(zg);
            hn = so * tanhf(cn);
            creg = cn;
            __stcg(&g_h[(size_t)(pout * 2 + dir) * 64 * 256 + b * 256 + hu], hn);
        }

        // arrive: release h store; then hide out-store + next xg gather
        gbar_arrive(ctr);
        if (kh == 0) {
            out[((size_t)b * Tl + tt) * 512 + dir * 256 + hu] = hn;
            if (t + 1 < Tl) {
                int tn = dir ? (Tl - 2 - t) : (t + 1);
                xg = __ldg((const float4*)&xw[((size_t)b * Tl + tn) * 1024 + (hu << 2)]);
            }
        }
        gbar_wait(ctr, epoch, nb);
    }
    if (kh == 0)
        g_c[(size_t)(dir * 64 + b) * 256 + hu] = creg;
}

// ---------------- persistent decoder (R7-proven) ----------------
#define DEC_SMEM ((16 * 1032 + 64 * 132 + 512 + 128 + 256 + 512 + 64 + 256) * 4)
__global__ __launch_bounds__(256) void dec_scan(
    const float* __restrict__ sWih, const float* __restrict__ sWhh,
    const float* __restrict__ sb, const int* __restrict__ gt,
    const float* __restrict__ phi_b,
    const float* __restrict__ fcW, const float* __restrict__ fcb,
    float* __restrict__ out_lps)
{
    extern __shared__ float smem[];
    float* sh_w  = smem;
    float* sh_x  = sh_w + 16 * 1032;
    float* sh_h  = sh_x + 64 * 132;
    float* sh_q  = sh_h + 512;
    float* sh_e  = sh_q + 128;
    float* sh_c2 = sh_e + 256;
    float* sh_l  = sh_c2 + 512;
    float* sr    = sh_l + 64;

    int tid = threadIdx.x;
    int lane = tid & 31, wrp = tid >> 5;
    int u = wrp & 3, bh = wrp >> 2;
    int b = bh * 32 + lane;
    int hu0 = blockIdx.x << 2;
    int hu = hu0 + u;
    unsigned epoch = 0;
    const unsigned nb = gridDim.x;
    unsigned* ctr = &g_barD;

    for (int i = tid; i < 16 * 256; i += 256) {
        int r = i >> 8, kq = (i & 255) << 2;
        int grow = (r >> 2) * SHID + hu0 + (r & 3);
        float4 v;
        if (kq < 512) v = *(const float4*)&sWih[(size_t)grow * 560 + 48 + kq];
        else          v = *(const float4*)&sWhh[(size_t)grow * 512 + (kq - 512)];
        *(float4*)&sh_w[r * 1032 + kq] = v;
    }

    float creg = 0.f;
    __stcg(&g_dh[(size_t)b * 512 + hu], 0.f);
    __stcg(&g_ctx[(size_t)b * 512 + hu], __ldg(&g_feats[(size_t)b * 256 * 512 + hu]));
    gbar(ctr, epoch, nb);

    float bi0 = sb[0 * SHID + hu], bi1 = sb[1 * SHID + hu];
    float bi2 = sb[2 * SHID + hu], bi3 = sb[3 * SHID + hu];

    for (int t = 0; t < TDEC; t++) {
        int pin = t & 1, pout = pin ^ 1;
        int tok = (t == 0) ? 0 : gt[b * TDEC + (t - 1)];
        U2 A0, A1, A2, A3;
        A0.f = make_float2(sWih[(size_t)(0 * SHID + hu) * 560 + tok] + bi0, 0.f);
        A1.f = make_float2(sWih[(size_t)(1 * SHID + hu) * 560 + tok] + bi1, 0.f);
        A2.f = make_float2(sWih[(size_t)(2 * SHID + hu) * 560 + tok] + bi2, 0.f);
        A3.f = make_float2(sWih[(size_t)(3 * SHID + hu) * 560 + tok] + bi3, 0.f);

        const float* hin = g_dh + (size_t)pin * 64 * 512;
        for (int c = 0; c < 8; c++) {
            __syncthreads();
            const float* src = (c < 4) ? (g_ctx + (c << 7)) : (hin + ((c - 4) << 7));
            for (int i = tid; i < 64 * 32; i += 256) {
                int bb = i >> 5, kq = (i & 31) << 2;
                *(float4*)&sh_x[bb * 132 + kq] = __ldcg((const float4*)&src[(size_t)bb * 512 + kq]);
            }
            __syncthreads();
            const float* wp = sh_w + c * 128;
#pragma unroll 8
            for (int kk = 0; kk < 128; kk += 4) {
                UP h, w0, w1, w2, w3;
                h.f  = *(const float4*)&sh_x[b * 132 + kk];
                w0.f = *(const float4*)&wp[(0 * 4 + u) * 1032 + kk];
                w1.f = *(const float4*)&wp[(1 * 4 + u) * 1032 + kk];
                w2.f = *(const float4*)&wp[(2 * 4 + u) * 1032 + kk];
                w3.f = *(const float4*)&wp[(3 * 4 + u) * 1032 + kk];
                fma2(A0.u, h.u[0], w0.u[0]); fma2(A1.u, h.u[0], w1.u[0]);
                fma2(A2.u, h.u[0], w2.u[0]); fma2(A3.u, h.u[0], w3.u[0]);
                fma2(A0.u, h.u[1], w0.u[1]); fma2(A1.u, h.u[1], w1.u[1]);
                fma2(A2.u, h.u[1], w2.u[1]); fma2(A3.u, h.u[1], w3.u[1]);
            }
        }
        float acc0 = A0.f.x + A0.f.y;
        float acc1 = A1.f.x + A1.f.y;
        float acc2 = A2.f.x + A2.f.y;
        float acc3 = A3.f.x + A3.f.y;
        float si = 1.f / (1.f + expf(-acc0));
        float sf = 1.f / (1.f + expf(-acc1));
        float so = 1.f / (1.f + expf(-acc3));
        float cn = sf * creg + si * tanhf(acc2);
        float hn = so * tanhf(cn);
        creg = cn;
        __stcg(&g_dh[(size_t)pout * 64 * 512 + b * 512 + hu], hn);
        gbar(ctr, epoch, nb);

        if (blockIdx.x < 64) {
            int bb = blockIdx.x;
            const float* h = g_dh + (size_t)pout * 64 * 512 + (size_t)bb * 512;
            for (int i = tid; i < 512; i += 256) sh_h[i] = __ldcg(&h[i]);
            __syncthreads();

            // phi GEMV: 256 threads, j = tid>>1 (0..127), half = tid&1
            {
                int j = tid >> 1, hf = tid & 1;
                const float* pw = g_phiWt + (size_t)hf * 256 * 128;
                const float* hh = sh_h + hf * 256;
                float a0 = 0.f, a1 = 0.f, a2 = 0.f, a3 = 0.f;
                for (int k = 0; k < 256; k += 4) {
                    a0 += hh[k + 0] * pw[(k + 0) * 128 + j];
                    a1 += hh[k + 1] * pw[(k + 1) * 128 + j];
                    a2 += hh[k + 2] * pw[(k + 2) * 128 + j];
                    a3 += hh[k + 3] * pw[(k + 3) * 128 + j];
                }
                sr[tid] = a0 + a1 + a2 + a3;
            }
            __syncthreads();
            if (tid < 128) {
                float q = sr[2 * tid] + sr[2 * tid + 1] + phi_b[tid];
                sh_q[tid] = q > 0.f ? q : 0.f;
            }
            __syncthreads();

            {
                const float* cfp = g_cf + ((size_t)bb * 256 + tid) * 128;
                float a0 = 0.f, a1 = 0.f, a2 = 0.f, a3 = 0.f;
                for (int j = 0; j < 128; j += 4) {
                    a0 += sh_q[j + 0] * cfp[j + 0];
                    a1 += sh_q[j + 1] * cfp[j + 1];
                    a2 += sh_q[j + 2] * cfp[j + 2];
                    a3 += sh_q[j + 3] * cfp[j + 3];
                }
                sh_e[tid] = a0 + a1 + a2 + a3;
            }
            __syncthreads();

            float v = sh_e[tid];
            sr[tid] = v; __syncthreads();
            for (int s = 128; s > 0; s >>= 1) { if (tid < s) sr[tid] = fmaxf(sr[tid], sr[tid + s]); __syncthreads(); }
            float m = sr[0]; __syncthreads();
            float e = expf(v - m);
            sr[tid] = e; __syncthreads();
            for (int s = 128; s > 0; s >>= 1) { if (tid < s) sr[tid] += sr[tid + s]; __syncthreads(); }
            float inv = 1.f / sr[0];
            __syncthreads();
            sh_e[tid] = e * inv;
            __syncthreads();

            for (int d0 = 0; d0 < 512; d0 += 256) {
                int d = d0 + tid;
                const float* fp = g_feats + (size_t)bb * 256 * 512 + d;
                float a0 = 0.f, a1 = 0.f, a2 = 0.f, a3 = 0.f;
                for (int tt2 = 0; tt2 < 256; tt2 += 4) {
                    a0 += sh_e[tt2 + 0] * fp[(size_t)(tt2 + 0) * 512];
                    a1 += sh_e[tt2 + 1] * fp[(size_t)(tt2 + 1) * 512];
                    a2 += sh_e[tt2 + 2] * fp[(size_t)(tt2 + 2) * 512];
                    a3 += sh_e[tt2 + 3] * fp[(size_t)(tt2 + 3) * 512];
                }
                float cv = a0 + a1 + a2 + a3;
                sh_c2[d] = cv;
                __stcg(&g_ctx[(size_t)bb * 512 + d], cv);
            }
            __syncthreads();

            if (tid < 192) {
                int v2 = tid >> 2, part = tid & 3;
                const float* wr = fcW + (size_t)v2 * 1024 + part * 256;
                const float* src = (part < 2) ? (sh_h + part * 256) : (sh_c2 + (part - 2) * 256);
                float a0 = 0.f, a1 = 0.f, a2 = 0.f, a3 = 0.f;
                for (int k = 0; k < 256; k += 4) {
                    a0 += src[k + 0] * wr[k + 0];
                    a1 += src[k + 1] * wr[k + 1];
                    a2 += src[k + 2] * wr[k + 2];
                    a3 += src[k + 3] * wr[k + 3];
                }
                sr[tid] = a0 + a1 + a2 + a3;
            }
            __syncthreads();
            if (tid < 48) {
                sh_l[tid] = sr[tid * 4] + sr[tid * 4 + 1] + sr[tid * 4 + 2] + sr[tid * 4 + 3] + fcb[tid];
            }
            __syncthreads();
            if (tid < 48) {
                float m2 = -1e30f;
                for (int j = 0; j < 48; j++) m2 = fmaxf(m2, sh_l[j]);
                float s2 = 0.f;
                for (int j = 0; j < 48; j++) s2 += expf(sh_l[j] - m2);
                out_lps[(size_t)bb * TDEC * NVOC + (size_t)t * NVOC + tid] = sh_l[tid] - m2 - logf(s2);
            }
        }
        gbar(ctr, epoch, nb);
    }
}

// ---------------- small helpers ----------------
__global__ void transpose_phi(const float* __restrict__ W) {
    int j = blockIdx.x;
    for (int k = threadIdx.x; k < 512; k += 256) g_phiWt[k * 128 + j] = W[j * 512 + k];
}

__global__ void fin_hc(float* __restrict__ out) {
    int b = blockIdx.x;
    for (int i = threadIdx.x; i < 1024; i += 256) {
        int q = i >> 8, r = i & 255;
        float v;
        if (q == 0)      v = g_h[(size_t)(0 * 2 + 0) * 64 * 256 + b * 256 + r];
        else if (q == 1) v = g_h[(size_t)(0 * 2 + 1) * 64 * 256 + b * 256 + r];
        else if (q == 2) v = g_c[(size_t)(0 * 64 + b) * 256 + r];
        else             v = g_c[(size_t)(1 * 64 + b) * 256 + r];
        out[(size_t)b * 1024 + i] = v;
    }
}

// ---------------- host launcher ----------------
extern "C" void kernel_launch(void* const* d_in, const int* in_sizes, int n_in,
                              void* d_out, int out_size)
{
    const float* inputs = (const float*)d_in[0];
    const int*   gt     = (const int*)d_in[1];
    const float* W[27];
    for (int i = 0; i < 27; i++) W[i] = (const float*)d_in[i + 2];

    float *xw0, *xw1, *out0, *out1, *feats, *cf;
    cudaGetSymbolAddress((void**)&xw0, g_xw0);
    cudaGetSymbolAddress((void**)&xw1, g_xw1);
    cudaGetSymbolAddress((void**)&out0, g_out0);
    cudaGetSymbolAddress((void**)&out1, g_out1);
    cudaGetSymbolAddress((void**)&feats, g_feats);
    cudaGetSymbolAddress((void**)&cf, g_cf);

    cudaFuncSetAttribute(enc_scan, cudaFuncAttributeMaxDynamicSharedMemorySize, ENC_SMEM);
    cudaFuncSetAttribute(dec_scan, cudaFuncAttributeMaxDynamicSharedMemorySize, DEC_SMEM);

    float* dout = (float*)d_out;

    reset_bars<<<1, 32>>>();
    nop_kernel<<<1, 32>>>();
    nop_kernel<<<1, 32>>>();

    // ---------------- encoder ----------------
    const float* A = inputs;
    float* outs[3] = {out0, out1, feats};
    int Tl = 1024, K = 160;
    unsigned ebase = 0;
    for (int l = 0; l < 3; l++) {
        int M = 64 * Tl;
        dim3 gg(1024 / 64, M / 128);
        gemm_bias<<<gg, 256>>>(A, W[l * 6 + 0], W[l * 6 + 2], xw0, M, 1024, K, 0, 1);
        gemm_bias<<<gg, 256>>>(A, W[l * 6 + 3], W[l * 6 + 5], xw1, M, 1024, K, 0, 1);
        enc_scan<<<dim3(64, 2), 512, ENC_SMEM>>>(xw0, xw1, W[l * 6 + 1], W[l * 6 + 4],
                                                 outs[l], Tl, ebase);
        ebase += 64u * (unsigned)(Tl + 1);
        A = outs[l];
        Tl >>= 1;
        K = 1024;
    }

    // comp_feat = relu(feats @ psi_W^T + psi_b)   [16384,128]
    gemm_bias<<<dim3(2, 16384 / 128), 256>>>(feats, W[23], W[24], cf, 16384, 128, 512, 1, 0);
    transpose_phi<<<128, 256>>>(W[21]);
    fin_hc<<<64, 256>>>(dout + (size_t)BATCH * TDEC * NVOC);

    // ---------------- decoder ----------------
    dec_scan<<<128, 256, DEC_SMEM>>>(W[18], W[19], W[20], gt, W[22], W[25], W[26], dout);
}